// round 12
// baseline (speedup 1.0000x reference)
#include <cuda_runtime.h>
#include <cuda_bf16.h>
#include <math.h>
#include <stdint.h>

#define Bv 8
#define Cv 512
#define Tv 1024
#define Hh 8
#define KCv 64

// ---------------------------------------------------------------------------
// Scratch (allocation-free rule: __device__ globals)
// ---------------------------------------------------------------------------
__device__ __nv_bfloat16 g_Whi[4 * Cv * Cv];
__device__ __nv_bfloat16 g_Wlo[4 * Cv * Cv];
__device__ __nv_bfloat16 g_Xhi[Bv * Tv * Cv];   // x^T split; later attention output
__device__ __nv_bfloat16 g_Xlo[Bv * Tv * Cv];
__device__ __nv_bfloat16 g_Chi[Bv * Tv * Cv];   // c^T split
__device__ __nv_bfloat16 g_Clo[Bv * Tv * Cv];
__device__ __nv_bfloat16 g_Qhi[Bv * Tv * Cv];   // Q split, [b][t][C], pre-scaled
__device__ __nv_bfloat16 g_Qlo[Bv * Tv * Cv];
__device__ __nv_bfloat16 g_Khi[Bv * Tv * Cv];   // K split, [b][t][C]
__device__ __nv_bfloat16 g_Klo[Bv * Tv * Cv];
__device__ __nv_bfloat16 g_Vhi[Bv * Cv * Tv];   // V split, [b][C][t]
__device__ __nv_bfloat16 g_Vlo[Bv * Cv * Tv];
__device__ uint32_t      g_BM[Bv * Tv * 32];    // mask bitmask

// ---------------------------------------------------------------------------
#define MMA16816(d, a, b) \
    asm volatile("mma.sync.aligned.m16n8k16.row.col.f32.bf16.bf16.f32 " \
        "{%0,%1,%2,%3}, {%4,%5,%6,%7}, {%8,%9}, {%0,%1,%2,%3};" \
        : "+f"((d)[0]), "+f"((d)[1]), "+f"((d)[2]), "+f"((d)[3]) \
        : "r"((a)[0]), "r"((a)[1]), "r"((a)[2]), "r"((a)[3]), \
          "r"((b)[0]), "r"((b)[1]))

#define CP_ASYNC16(saddr, gptr) \
    asm volatile("cp.async.cg.shared.global [%0], [%1], 16;" \
                 :: "r"(saddr), "l"(gptr) : "memory")
#define CP_COMMIT() asm volatile("cp.async.commit_group;" ::: "memory")
#define CP_WAIT1()  asm volatile("cp.async.wait_group 1;" ::: "memory")
#define CP_WAIT0()  asm volatile("cp.async.wait_group 0;" ::: "memory")

__device__ __forceinline__ uint32_t ldb32(const __nv_bfloat16* p) {
    return *reinterpret_cast<const uint32_t*>(p);
}
__device__ __forceinline__ uint32_t s2u(const void* p) {
    return (uint32_t)__cvta_generic_to_shared(p);
}
__device__ __forceinline__ void pack_pair(float x, float y, uint32_t& hi, uint32_t& lo) {
    const __nv_bfloat16 hx = __float2bfloat16(x), hy = __float2bfloat16(y);
    const __nv_bfloat16 lx = __float2bfloat16(x - __bfloat162float(hx));
    const __nv_bfloat16 ly = __float2bfloat16(y - __bfloat162float(hy));
    __nv_bfloat162 h2; h2.x = hx; h2.y = hy;
    __nv_bfloat162 l2; l2.x = lx; l2.y = ly;
    hi = *reinterpret_cast<const uint32_t*>(&h2);
    lo = *reinterpret_cast<const uint32_t*>(&l2);
}

// ---------------------------------------------------------------------------
// fp32 -> (hi, lo) bf16 split for 4 weight matrices in one launch
// ---------------------------------------------------------------------------
__global__ __launch_bounds__(256) void convw4_kernel(
    const float* __restrict__ w0, const float* __restrict__ w1,
    const float* __restrict__ w2, const float* __restrict__ w3)
{
    const int m = blockIdx.y;
    const float* w = (m == 0) ? w0 : (m == 1) ? w1 : (m == 2) ? w2 : w3;
    const int i = blockIdx.x * 256 + threadIdx.x;
    const float v = w[i];
    const __nv_bfloat16 h = __float2bfloat16(v);
    g_Whi[m * Cv * Cv + i] = h;
    g_Wlo[m * Cv * Cv + i] = __float2bfloat16(v - __bfloat162float(h));
}

// ---------------------------------------------------------------------------
// Fused: [b][c][t] fp32 -> [b][t][c] bf16 hi/lo for BOTH x and c.
// grid (T/32, C/32, 2B); z < B: x -> Xhi/Xlo; else c -> Chi/Clo.
// ---------------------------------------------------------------------------
__global__ __launch_bounds__(256) void tconv2_kernel(
    const float* __restrict__ inx, const float* __restrict__ inc)
{
    __shared__ float tile[32][33];
    const int zz = blockIdx.z;
    const int b = (zz < Bv) ? zz : zz - Bv;
    const float* in = (zz < Bv) ? inx : inc;
    __nv_bfloat16* hi = (zz < Bv) ? g_Xhi : g_Chi;
    __nv_bfloat16* lo = (zz < Bv) ? g_Xlo : g_Clo;
    const int c0 = blockIdx.y * 32, t0 = blockIdx.x * 32;
    const int tx = threadIdx.x, ty = threadIdx.y;
    const float* src = in + ((size_t)b * Cv + c0) * Tv + t0;
#pragma unroll
    for (int i = ty; i < 32; i += 8)
        tile[i][tx] = src[(size_t)i * Tv + tx];
    __syncthreads();
#pragma unroll
    for (int i = ty; i < 32; i += 8) {
        const float v = tile[tx][i];
        const size_t o = ((size_t)b * Tv + t0 + i) * Cv + c0 + tx;
        const __nv_bfloat16 h = __float2bfloat16(v);
        hi[o] = h;
        lo[o] = __float2bfloat16(v - __bfloat162float(h));
    }
}

// ---------------------------------------------------------------------------
// mask -> bitmask
// ---------------------------------------------------------------------------
__global__ __launch_bounds__(256) void maskbits_kernel(const float* __restrict__ mask)
{
    const int b = blockIdx.y;
    const int t = blockIdx.x * 8 + (threadIdx.x >> 5);
    const int lane = threadIdx.x & 31;
    const float* row = mask + ((size_t)b * Tv + t) * Tv;
    uint32_t* dst = g_BM + ((size_t)b * Tv + t) * 32;
#pragma unroll 4
    for (int wd = 0; wd < 32; wd++) {
        const float v = row[wd * 32 + lane];
        const uint32_t word = __ballot_sync(0xffffffffu, v != 0.f);
        if (lane == 0) dst[wd] = word;
    }
}

// ---------------------------------------------------------------------------
// cp.async double-buffered GEMM core pieces
// ---------------------------------------------------------------------------
#define KCH 32
#define SSTR 40
#define GARR (128 * SSTR)
#define GSTAGE (4 * GARR)
#define GEMM_SMEM_BYTES (2 * GSTAGE * 2)

__device__ __forceinline__ void gemm_stage_cp(
    __nv_bfloat16* st, const __nv_bfloat16* pAh, const __nv_bfloat16* pAl,
    const __nv_bfloat16* pBh, const __nv_bfloat16* pBl, int kc0, int tid)
{
    __nv_bfloat16* sAh = st;
    __nv_bfloat16* sAl = st + GARR;
    __nv_bfloat16* sBh = st + 2 * GARR;
    __nv_bfloat16* sBl = st + 3 * GARR;
#pragma unroll
    for (int u = 0; u < 2; u++) {
        const int idx = tid + u * 256;
        const int r = idx >> 2, c8 = (idx & 3) * 8;
        const size_t go = (size_t)r * Cv + kc0 + c8;
        const uint32_t so = (uint32_t)(r * SSTR + c8);
        CP_ASYNC16(s2u(sAh + so), pAh + go);
        CP_ASYNC16(s2u(sAl + so), pAl + go);
        CP_ASYNC16(s2u(sBh + so), pBh + go);
        CP_ASYNC16(s2u(sBl + so), pBl + go);
    }
}

// mainloop: fills acc from pA*, pB*
__device__ __forceinline__ void gemm_mainloop(
    __nv_bfloat16* gsm, const __nv_bfloat16* pAh, const __nv_bfloat16* pAl,
    const __nv_bfloat16* pBh, const __nv_bfloat16* pBl,
    float acc[4][4][4], int tid, int m0, int n0, int g, int tg)
{
    gemm_stage_cp(gsm, pAh, pAl, pBh, pBl, 0, tid);
    CP_COMMIT();

    for (int kc0 = 0, it = 0; kc0 < Cv; kc0 += KCH, it++) {
        if (kc0 + KCH < Cv) {
            gemm_stage_cp(gsm + ((it + 1) & 1) * GSTAGE, pAh, pAl, pBh, pBl,
                          kc0 + KCH, tid);
            CP_COMMIT();
            CP_WAIT1();
        } else {
            CP_WAIT0();
        }
        __syncthreads();

        const __nv_bfloat16* st = gsm + (it & 1) * GSTAGE;
        const __nv_bfloat16* sAh = st;
        const __nv_bfloat16* sAl = st + GARR;
        const __nv_bfloat16* sBh = st + 2 * GARR;
        const __nv_bfloat16* sBl = st + 3 * GARR;

#pragma unroll
        for (int ks = 0; ks < KCH; ks += 16) {
            const int kk = ks + tg * 2;
            uint32_t ah[4][4], al[4][4], bh[4][2], bl[4][2];
#pragma unroll
            for (int mi = 0; mi < 4; mi++) {
                const int row = m0 + mi * 16 + g;
                ah[mi][0] = ldb32(&sAh[row * SSTR + kk]);
                ah[mi][1] = ldb32(&sAh[(row + 8) * SSTR + kk]);
                ah[mi][2] = ldb32(&sAh[row * SSTR + kk + 8]);
                ah[mi][3] = ldb32(&sAh[(row + 8) * SSTR + kk + 8]);
                al[mi][0] = ldb32(&sAl[row * SSTR + kk]);
                al[mi][1] = ldb32(&sAl[(row + 8) * SSTR + kk]);
                al[mi][2] = ldb32(&sAl[row * SSTR + kk + 8]);
                al[mi][3] = ldb32(&sAl[(row + 8) * SSTR + kk + 8]);
            }
#pragma unroll
            for (int nj = 0; nj < 4; nj++) {
                const int col = n0 + nj * 8 + g;
                bh[nj][0] = ldb32(&sBh[col * SSTR + kk]);
                bh[nj][1] = ldb32(&sBh[col * SSTR + kk + 8]);
                bl[nj][0] = ldb32(&sBl[col * SSTR + kk]);
                bl[nj][1] = ldb32(&sBl[col * SSTR + kk + 8]);
            }
#pragma unroll
            for (int mi = 0; mi < 4; mi++)
#pragma unroll
                for (int nj = 0; nj < 4; nj++) {
                    MMA16816(acc[mi][nj], ah[mi], bh[nj]);
                    MMA16816(acc[mi][nj], ah[mi], bl[nj]);
                    MMA16816(acc[mi][nj], al[mi], bh[nj]);
                }
        }
        __syncthreads();
    }
}

// ---------------------------------------------------------------------------
// Fused Q/K/V projection: grid (32, 3, B), block 256.
// proj 0: Q = x.Wq^T (MODE0 epilogue -> g_Q [b][t][C], scale 1/8)
// proj 1: K = c.Wk^T (MODE0 epilogue -> g_K [b][t][C])
// proj 2: V = Wv.c^T (MODE1 epilogue -> g_V [b][C][t])
// ---------------------------------------------------------------------------
__global__ __launch_bounds__(256, 2) void hmma_qkv(
    const float* __restrict__ bq, const float* __restrict__ bk,
    const float* __restrict__ bv)
{
    extern __shared__ __align__(16) __nv_bfloat16 gsm[];

    const int tile = blockIdx.x, proj = blockIdx.y, b = blockIdx.z;
    const int tid = threadIdx.x, wid = tid >> 5, lid = tid & 31;
    const int wm = wid >> 2, wn = wid & 3;
    const int m0 = wm * 64, n0 = wn * 32;
    const int g = lid >> 2, tg = lid & 3;

    int mblk, nblk;
    const __nv_bfloat16 *pAh, *pAl, *pBh, *pBl;
    const float* bias;
    float scale = 1.0f;
    if (proj == 0) {
        nblk = (tile & 3) * 128; mblk = (tile >> 2) * 128;
        pAh = g_Xhi + ((size_t)b * Tv + mblk) * Cv;
        pAl = g_Xlo + ((size_t)b * Tv + mblk) * Cv;
        pBh = g_Whi + (size_t)nblk * Cv;
        pBl = g_Wlo + (size_t)nblk * Cv;
        bias = bq; scale = 0.125f;
    } else if (proj == 1) {
        nblk = (tile & 3) * 128; mblk = (tile >> 2) * 128;
        pAh = g_Chi + ((size_t)b * Tv + mblk) * Cv;
        pAl = g_Clo + ((size_t)b * Tv + mblk) * Cv;
        pBh = g_Whi + Cv * Cv + (size_t)nblk * Cv;
        pBl = g_Wlo + Cv * Cv + (size_t)nblk * Cv;
        bias = bk;
    } else {
        mblk = (tile & 3) * 128; nblk = (tile >> 2) * 128;
        pAh = g_Whi + 2 * Cv * Cv + (size_t)mblk * Cv;
        pAl = g_Wlo + 2 * Cv * Cv + (size_t)mblk * Cv;
        pBh = g_Chi + ((size_t)b * Tv + nblk) * Cv;
        pBl = g_Clo + ((size_t)b * Tv + nblk) * Cv;
        bias = bv;
    }

    float acc[4][4][4];
#pragma unroll
    for (int mi = 0; mi < 4; mi++)
#pragma unroll
        for (int nj = 0; nj < 4; nj++)
#pragma unroll
            for (int r = 0; r < 4; r++) acc[mi][nj][r] = 0.f;

    gemm_mainloop(gsm, pAh, pAl, pBh, pBl, acc, tid, m0, n0, g, tg);

    if (proj < 2) {
        __nv_bfloat16* ohi = (proj == 0) ? g_Qhi : g_Khi;
        __nv_bfloat16* olo = (proj == 0) ? g_Qlo : g_Klo;
#pragma unroll
        for (int mi = 0; mi < 4; mi++) {
            const int t0r = mblk + m0 + mi * 16 + g;
#pragma unroll
            for (int nj = 0; nj < 4; nj++) {
                const int o = nblk + n0 + nj * 8 + tg * 2;
                const float b0 = bias[o], b1 = bias[o + 1];
                uint32_t hw, lw;
                pack_pair((acc[mi][nj][0] + b0) * scale, (acc[mi][nj][1] + b1) * scale, hw, lw);
                const size_t a0 = ((size_t)b * Tv + t0r) * Cv + o;
                *reinterpret_cast<uint32_t*>(&ohi[a0]) = hw;
                *reinterpret_cast<uint32_t*>(&olo[a0]) = lw;
                pack_pair((acc[mi][nj][2] + b0) * scale, (acc[mi][nj][3] + b1) * scale, hw, lw);
                const size_t a1 = ((size_t)b * Tv + t0r + 8) * Cv + o;
                *reinterpret_cast<uint32_t*>(&ohi[a1]) = hw;
                *reinterpret_cast<uint32_t*>(&olo[a1]) = lw;
            }
        }
    } else {
#pragma unroll
        for (int mi = 0; mi < 4; mi++) {
            const int o = mblk + m0 + mi * 16 + g;
            const float b0 = bias[o], b1 = bias[o + 8];
#pragma unroll
            for (int nj = 0; nj < 4; nj++) {
                const int t = nblk + n0 + nj * 8 + tg * 2;
                uint32_t hw, lw;
                pack_pair(acc[mi][nj][0] + b0, acc[mi][nj][1] + b0, hw, lw);
                const size_t a0 = ((size_t)b * Cv + o) * Tv + t;
                *reinterpret_cast<uint32_t*>(&g_Vhi[a0]) = hw;
                *reinterpret_cast<uint32_t*>(&g_Vlo[a0]) = lw;
                pack_pair(acc[mi][nj][2] + b1, acc[mi][nj][3] + b1, hw, lw);
                const size_t a1 = ((size_t)b * Cv + o + 8) * Tv + t;
                *reinterpret_cast<uint32_t*>(&g_Vhi[a1]) = hw;
                *reinterpret_cast<uint32_t*>(&g_Vlo[a1]) = lw;
            }
        }
    }
}

// ---------------------------------------------------------------------------
// Final projection: out = Wo . attnout^T (fp32 [b][C][t]) — cp.async pipeline
// grid (T/128, C/128, B)
// ---------------------------------------------------------------------------
__global__ __launch_bounds__(256, 2) void hmma_out(
    const float* __restrict__ bias, float* __restrict__ outf)
{
    extern __shared__ __align__(16) __nv_bfloat16 gsm[];

    const int nblk = blockIdx.x * 128, mblk = blockIdx.y * 128, b = blockIdx.z;
    const int tid = threadIdx.x, wid = tid >> 5, lid = tid & 31;
    const int wm = wid >> 2, wn = wid & 3;
    const int m0 = wm * 64, n0 = wn * 32;
    const int g = lid >> 2, tg = lid & 3;

    const __nv_bfloat16* pAh = g_Whi + 3 * Cv * Cv + (size_t)mblk * Cv;
    const __nv_bfloat16* pAl = g_Wlo + 3 * Cv * Cv + (size_t)mblk * Cv;
    const __nv_bfloat16* pBh = g_Xhi + ((size_t)b * Tv + nblk) * Cv;
    const __nv_bfloat16* pBl = g_Xlo + ((size_t)b * Tv + nblk) * Cv;

    float acc[4][4][4];
#pragma unroll
    for (int mi = 0; mi < 4; mi++)
#pragma unroll
        for (int nj = 0; nj < 4; nj++)
#pragma unroll
            for (int r = 0; r < 4; r++) acc[mi][nj][r] = 0.f;

    gemm_mainloop(gsm, pAh, pAl, pBh, pBl, acc, tid, m0, n0, g, tg);

#pragma unroll
    for (int mi = 0; mi < 4; mi++) {
        const int o = mblk + m0 + mi * 16 + g;
        const float b0 = bias[o], b1 = bias[o + 8];
#pragma unroll
        for (int nj = 0; nj < 4; nj++) {
            const int t = nblk + n0 + nj * 8 + tg * 2;
            float2 v0, v1;
            v0.x = acc[mi][nj][0] + b0;
            v0.y = acc[mi][nj][1] + b0;
            v1.x = acc[mi][nj][2] + b1;
            v1.y = acc[mi][nj][3] + b1;
            *reinterpret_cast<float2*>(&outf[((size_t)b * Cv + o) * Tv + t]) = v0;
            *reinterpret_cast<float2*>(&outf[((size_t)b * Cv + o + 8) * Tv + t]) = v1;
        }
    }
}

// ---------------------------------------------------------------------------
// HMMA banded flash attention. Fixed-shift softmax (shift -20 folded into
// sBias; exact by shift invariance — logits bounded ~|10|, overflow needs
// s > 108). grid (T/128, H, B), block 256, 2 CTAs/SM, per-warp chunk skip.
// ---------------------------------------------------------------------------
#define QSTR 72

#define OFF_QH 0
#define OFF_QL (128 * QSTR)
#define OFF_KH (2 * 128 * QSTR)
#define OFF_KL (2 * 128 * QSTR + 64 * QSTR)
#define OFF_VH (2 * 128 * QSTR + 2 * 64 * QSTR)
#define OFF_VL (2 * 128 * QSTR + 3 * 64 * QSTR)
#define BF16_ELEMS (2 * 128 * QSTR + 4 * 64 * QSTR)
#define F_RK   0
#define F_BIAS (128 * 12)
#define F_EV   (128 * 12 + 516)
#define F_EK   (128 * 12 + 516 + 576)
#define F_PD   (128 * 12 + 516 + 2 * 576)
#define F_TOTAL (2 * 128 * 12 + 516 + 2 * 576)
#define ATTN_SMEM_BYTES (BF16_ELEMS * 2 + F_TOTAL * 4)
#define SOFTMAX_SHIFT 20.0f

__global__ __launch_bounds__(256, 2) void attn_hmma(
    const float* __restrict__ ek, const float* __restrict__ ev)
{
    extern __shared__ __align__(16) char smem_raw[];
    __nv_bfloat16* sB16 = reinterpret_cast<__nv_bfloat16*>(smem_raw);
    float* sF = reinterpret_cast<float*>(smem_raw + BF16_ELEMS * 2);
    __nv_bfloat16* sQh = sB16 + OFF_QH;
    __nv_bfloat16* sQl = sB16 + OFF_QL;
    __nv_bfloat16* sKh = sB16 + OFF_KH;
    __nv_bfloat16* sKl = sB16 + OFF_KL;
    __nv_bfloat16* sVh = sB16 + OFF_VH;
    __nv_bfloat16* sVl = sB16 + OFF_VL;
    float* sRK   = sF + F_RK;
    float* sBias = sF + F_BIAS;
    float* sEV   = sF + F_EV;
    float* sEK   = sF + F_EK;
    float* sPd   = sF + F_PD;

    const int t0 = blockIdx.x * 128;
    const int h  = blockIdx.y;
    const int b  = blockIdx.z;
    const int tid = threadIdx.x, wid = tid >> 5, lid = tid & 31;
    const int g = lid >> 2, tg = lid & 3;
    const int wloc = wid * 16;

    const __nv_bfloat16* Kh_b = g_Khi + ((size_t)b * Tv) * Cv + h * 64;
    const __nv_bfloat16* Kl_b = g_Klo + ((size_t)b * Tv) * Cv + h * 64;
    const __nv_bfloat16* Vh_b = g_Vhi + ((size_t)b * Cv + h * 64) * Tv;
    const __nv_bfloat16* Vl_b = g_Vlo + ((size_t)b * Cv + h * 64) * Tv;
    const size_t qrow0 = ((size_t)b * Tv + t0) * Cv + h * 64;

    for (int i = tid; i < 1024; i += 256) {
        const int t = i >> 3, seg = (i & 7) * 8;
        *reinterpret_cast<uint4*>(&sQh[t * QSTR + seg]) =
            *reinterpret_cast<const uint4*>(&g_Qhi[qrow0 + (size_t)t * Cv + seg]);
        *reinterpret_cast<uint4*>(&sQl[t * QSTR + seg]) =
            *reinterpret_cast<const uint4*>(&g_Qlo[qrow0 + (size_t)t * Cv + seg]);
    }
    for (int i = tid; i < 513; i += 256)
        sBias[i] = -log1pf(fabsf((float)(i - 256))) - SOFTMAX_SHIFT;
    for (int i = tid; i < 576; i += 256) { sEK[i] = ek[i]; sEV[i] = ev[i]; }
    __syncthreads();

    for (int i = tid; i < 1152; i += 256) {
        const int tl = i & 127, dd = i >> 7;
        float s = 0.f;
#pragma unroll 16
        for (int kc = 0; kc < 64; kc++) {
            const float q = __bfloat162float(sQh[tl * QSTR + kc]) +
                            __bfloat162float(sQl[tl * QSTR + kc]);
            s += q * sEK[dd * 64 + kc];
        }
        sRK[tl * 12 + dd] = s;
    }

    float l0 = 0.f, l1 = 0.f;
    float O[8][4];
#pragma unroll
    for (int nt = 0; nt < 8; nt++)
#pragma unroll
        for (int r = 0; r < 4; r++) O[nt][r] = 0.f;

    const int s_lo = max(0, t0 - 256);
    const int s_hi = min(Tv, t0 + 128 + 256);

    for (int s0 = s_lo; s0 < s_hi; s0 += 64) {
        const bool window = (s0 >= t0 - 64) && (s0 <= t0 + 128);
        const bool active = (s0 + 63 >= t0 + wloc - 256) && (s0 <= t0 + wloc + 15 + 256);
        __syncthreads();
        if (window) {
            for (int i = tid; i < 1536; i += 256) sPd[i] = 0.f;
        }
#pragma unroll
        for (int u = 0; u < 2; u++) {
            const int idx = tid + u * 256;
            const int fr = idx >> 3, fseg = (idx & 7) * 8;
            *reinterpret_cast<uint4*>(&sKh[fr * QSTR + fseg]) =
                *reinterpret_cast<const uint4*>(&Kh_b[(size_t)(s0 + fr) * Cv + fseg]);
            *reinterpret_cast<uint4*>(&sKl[fr * QSTR + fseg]) =
                *reinterpret_cast<const uint4*>(&Kl_b[(size_t)(s0 + fr) * Cv + fseg]);
            *reinterpret_cast<uint4*>(&sVh[fr * QSTR + fseg]) =
                *reinterpret_cast<const uint4*>(&Vh_b[(size_t)fr * Tv + s0 + fseg]);
            *reinterpret_cast<uint4*>(&sVl[fr * QSTR + fseg]) =
                *reinterpret_cast<const uint4*>(&Vl_b[(size_t)fr * Tv + s0 + fseg]);
        }
        __syncthreads();

        if (!active) continue;

        const int w0 = s0 >> 5;
        const int row0 = t0 + wloc + g;
        const uint32_t bA0 = g_BM[((size_t)b * Tv + row0) * 32 + w0];
        const uint32_t bA1 = g_BM[((size_t)b * Tv + row0) * 32 + w0 + 1];
        const uint32_t bB0 = g_BM[((size_t)b * Tv + row0 + 8) * 32 + w0];
        const uint32_t bB1 = g_BM[((size_t)b * Tv + row0 + 8) * 32 + w0 + 1];

        // ---- S = Q K^T ----
        float S[8][4];
#pragma unroll
        for (int nt = 0; nt < 8; nt++)
#pragma unroll
            for (int r = 0; r < 4; r++) S[nt][r] = 0.f;

#pragma unroll
        for (int ks = 0; ks < 4; ks++) {
            const int qr = (wloc + g) * QSTR + ks * 16 + tg * 2;
            uint32_t aqh[4], aql[4];
            aqh[0] = ldb32(&sQh[qr]);
            aqh[1] = ldb32(&sQh[qr + 8 * QSTR]);
            aqh[2] = ldb32(&sQh[qr + 8]);
            aqh[3] = ldb32(&sQh[qr + 8 * QSTR + 8]);
            aql[0] = ldb32(&sQl[qr]);
            aql[1] = ldb32(&sQl[qr + 8 * QSTR]);
            aql[2] = ldb32(&sQl[qr + 8]);
            aql[3] = ldb32(&sQl[qr + 8 * QSTR + 8]);
#pragma unroll
            for (int nt = 0; nt < 8; nt++) {
                const int kr = (nt * 8 + g) * QSTR + ks * 16 + tg * 2;
                uint32_t bh[2], bl[2];
                bh[0] = ldb32(&sKh[kr]);
                bh[1] = ldb32(&sKh[kr + 8]);
                bl[0] = ldb32(&sKl[kr]);
                bl[1] = ldb32(&sKl[kr + 8]);
                MMA16816(S[nt], aqh, bh);
                MMA16816(S[nt], aqh, bl);
                MMA16816(S[nt], aql, bh);
            }
        }

        // ---- biases + band + mask + exp (fixed shift), accumulate l ----
        float rs0 = 0.f, rs1 = 0.f;
#pragma unroll
        for (int nt = 0; nt < 8; nt++) {
#pragma unroll
            for (int r = 0; r < 4; r++) {
                const int tlr = wloc + g + ((r >> 1) << 3);
                const int t = t0 + tlr;
                const int si = nt * 8 + tg * 2 + (r & 1);
                const int s = s0 + si;
                const int d = s - t;
                float v = S[nt][r];
                if (d >= -256 && d <= 256) {
                    v += sBias[d + 256];
                    if (d >= -4 && d <= 4) v += sRK[tlr * 12 + d + 4];
                    const uint32_t wv = (r >> 1) ? ((si >= 32) ? bB1 : bB0)
                                                 : ((si >= 32) ? bA1 : bA0);
                    if (!((wv >> (si & 31)) & 1u)) v = -2e30f;
                } else {
                    v = -2e30f;
                }
                const float p = __expf(v);
                S[nt][r] = p;
                if (r < 2) rs0 += p; else rs1 += p;
            }
        }
        rs0 += __shfl_xor_sync(0xffffffffu, rs0, 1);
        rs0 += __shfl_xor_sync(0xffffffffu, rs0, 2);
        rs1 += __shfl_xor_sync(0xffffffffu, rs1, 1);
        rs1 += __shfl_xor_sync(0xffffffffu, rs1, 2);
        l0 += rs0; l1 += rs1;

        // stash diagonal p's for rel-value stencil (sPd rows warp-exclusive)
        if (window) {
#pragma unroll
            for (int nt = 0; nt < 8; nt++) {
#pragma unroll
                for (int r = 0; r < 4; r++) {
                    const int tlr = wloc + g + ((r >> 1) << 3);
                    const int d = (s0 + nt * 8 + tg * 2 + (r & 1)) - (t0 + tlr);
                    if (d >= -4 && d <= 4) sPd[tlr * 12 + d + 4] = S[nt][r];
                }
            }
        }

        // ---- O += P V ----
#pragma unroll
        for (int ks = 0; ks < 4; ks++) {
            uint32_t aph[4], apl[4];
            pack_pair(S[2 * ks][0],     S[2 * ks][1],     aph[0], apl[0]);
            pack_pair(S[2 * ks][2],     S[2 * ks][3],     aph[1], apl[1]);
            pack_pair(S[2 * ks + 1][0], S[2 * ks + 1][1], aph[2], apl[2]);
            pack_pair(S[2 * ks + 1][2], S[2 * ks + 1][3], aph[3], apl[3]);
#pragma unroll
            for (int nt = 0; nt < 8; nt++) {
                const int vr = (nt * 8 + g) * QSTR + ks * 16 + tg * 2;
                uint32_t bh[2], bl[2];
                bh[0] = ldb32(&sVh[vr]);
                bh[1] = ldb32(&sVh[vr + 8]);
                bl[0] = ldb32(&sVl[vr]);
                bl[1] = ldb32(&sVl[vr + 8]);
                MMA16816(O[nt], aph, bh);
                MMA16816(O[nt], aph, bl);
                MMA16816(O[nt], apl, bh);
            }
        }

        // ---- rel-value 9-tap stencil (same-warp rows) ----
        if (window) {
            __syncwarp();
#pragma unroll
            for (int rh = 0; rh < 2; rh++) {
                const int tlr = wloc + g + rh * 8;
#pragma unroll
                for (int dd = 0; dd < 9; dd++) {
                    const float p = sPd[tlr * 12 + dd];
                    if (p != 0.f) {
#pragma unroll
                        for (int nt = 0; nt < 8; nt++) {
                            O[nt][2 * rh]     += p * sEV[dd * 64 + nt * 8 + tg * 2];
                            O[nt][2 * rh + 1] += p * sEV[dd * 64 + nt * 8 + tg * 2 + 1];
                        }
                    }
                }
            }
        }
    }

    // ---- finalize ----
    const float inv0 = 1.f / l0, inv1 = 1.f / l1;
    const size_t out0 = ((size_t)b * Tv + t0 + wloc + g) * Cv + h * 64;
    const size_t out1 = out0 + 8 * Cv;
#pragma unroll
    for (int nt = 0; nt < 8; nt++) {
        const int kc = nt * 8 + tg * 2;
        uint32_t hw, lw;
        pack_pair(O[nt][0] * inv0, O[nt][1] * inv0, hw, lw);
        *reinterpret_cast<uint32_t*>(&g_Xhi[out0 + kc]) = hw;
        *reinterpret_cast<uint32_t*>(&g_Xlo[out0 + kc]) = lw;
        pack_pair(O[nt][2] * inv1, O[nt][3] * inv1, hw, lw);
        *reinterpret_cast<uint32_t*>(&g_Xhi[out1 + kc]) = hw;
        *reinterpret_cast<uint32_t*>(&g_Xlo[out1 + kc]) = lw;
    }
}

// ---------------------------------------------------------------------------

extern "C" void kernel_launch(void* const* d_in, const int* in_sizes, int n_in,
                              void* d_out, int out_size)
{
    const float* x    = (const float*)d_in[0];
    const float* c    = (const float*)d_in[1];
    const float* mask = (const float*)d_in[2];
    const float* Wq   = (const float*)d_in[3];
    const float* bq   = (const float*)d_in[4];
    const float* Wk   = (const float*)d_in[5];
    const float* bk   = (const float*)d_in[6];
    const float* Wv   = (const float*)d_in[7];
    const float* bv   = (const float*)d_in[8];
    const float* Wo   = (const float*)d_in[9];
    const float* bo   = (const float*)d_in[10];
    const float* ek   = (const float*)d_in[11];
    const float* ev   = (const float*)d_in[12];
    float* out = (float*)d_out;

    cudaFuncSetAttribute(attn_hmma, cudaFuncAttributeMaxDynamicSharedMemorySize,
                         ATTN_SMEM_BYTES);
    cudaFuncSetAttribute(hmma_qkv, cudaFuncAttributeMaxDynamicSharedMemorySize,
                         GEMM_SMEM_BYTES);
    cudaFuncSetAttribute(hmma_out, cudaFuncAttributeMaxDynamicSharedMemorySize,
                         GEMM_SMEM_BYTES);

    const int WSZ = Cv * Cv;

    // pre-passes
    dim3 wg(WSZ / 256, 4);
    convw4_kernel<<<wg, 256>>>(Wq, Wk, Wv, Wo);
    dim3 tg(Tv / 32, Cv / 32, 2 * Bv), tb(32, 8);
    tconv2_kernel<<<tg, tb>>>(x, c);
    maskbits_kernel<<<dim3(Tv / 8, Bv), 256>>>(mask);

    // fused Q/K/V projections
    hmma_qkv<<<dim3(32, 3, Bv), 256, GEMM_SMEM_BYTES>>>(bq, bk, bv);

    // attention (writes split output into g_Xhi/g_Xlo)
    attn_hmma<<<dim3(Tv / 128, Hh, Bv), 256, ATTN_SMEM_BYTES>>>(ek, ev);

    // final projection (fp32 output)
    hmma_out<<<dim3(Tv / 128, Cv / 128, Bv), 256, GEMM_SMEM_BYTES>>>(bo, out);
}

// round 13
// speedup vs baseline: 1.4662x; 1.4662x over previous
#include <cuda_runtime.h>
#include <cuda_bf16.h>
#include <math.h>
#include <stdint.h>

#define Bv 8
#define Cv 512
#define Tv 1024
#define Hh 8
#define KCv 64

// ---------------------------------------------------------------------------
// Scratch (allocation-free rule: __device__ globals)
// ---------------------------------------------------------------------------
__device__ __nv_bfloat16 g_Whi[4 * Cv * Cv];
__device__ __nv_bfloat16 g_Wlo[4 * Cv * Cv];
__device__ __nv_bfloat16 g_Xhi[Bv * Tv * Cv];   // x^T split; later attention output
__device__ __nv_bfloat16 g_Xlo[Bv * Tv * Cv];
__device__ __nv_bfloat16 g_Chi[Bv * Tv * Cv];   // c^T split
__device__ __nv_bfloat16 g_Clo[Bv * Tv * Cv];
__device__ __nv_bfloat16 g_Qhi[Bv * Tv * Cv];   // Q split, [b][t][C], pre-scaled
__device__ __nv_bfloat16 g_Qlo[Bv * Tv * Cv];
__device__ __nv_bfloat16 g_Khi[Bv * Tv * Cv];   // K split, [b][t][C]
__device__ __nv_bfloat16 g_Klo[Bv * Tv * Cv];
__device__ __nv_bfloat16 g_Vhi[Bv * Cv * Tv];   // V split, [b][C][t]
__device__ __nv_bfloat16 g_Vlo[Bv * Cv * Tv];
__device__ uint32_t      g_BM[Bv * Tv * 32];    // mask bitmask

// ---------------------------------------------------------------------------
#define MMA16816(d, a, b) \
    asm volatile("mma.sync.aligned.m16n8k16.row.col.f32.bf16.bf16.f32 " \
        "{%0,%1,%2,%3}, {%4,%5,%6,%7}, {%8,%9}, {%0,%1,%2,%3};" \
        : "+f"((d)[0]), "+f"((d)[1]), "+f"((d)[2]), "+f"((d)[3]) \
        : "r"((a)[0]), "r"((a)[1]), "r"((a)[2]), "r"((a)[3]), \
          "r"((b)[0]), "r"((b)[1]))

#define CP_ASYNC16(saddr, gptr) \
    asm volatile("cp.async.cg.shared.global [%0], [%1], 16;" \
                 :: "r"(saddr), "l"(gptr) : "memory")
#define CP_COMMIT() asm volatile("cp.async.commit_group;" ::: "memory")
#define CP_WAIT1()  asm volatile("cp.async.wait_group 1;" ::: "memory")
#define CP_WAIT0()  asm volatile("cp.async.wait_group 0;" ::: "memory")

__device__ __forceinline__ uint32_t ldb32(const __nv_bfloat16* p) {
    return *reinterpret_cast<const uint32_t*>(p);
}
__device__ __forceinline__ uint32_t s2u(const void* p) {
    return (uint32_t)__cvta_generic_to_shared(p);
}
__device__ __forceinline__ void pack_pair(float x, float y, uint32_t& hi, uint32_t& lo) {
    const __nv_bfloat16 hx = __float2bfloat16(x), hy = __float2bfloat16(y);
    const __nv_bfloat16 lx = __float2bfloat16(x - __bfloat162float(hx));
    const __nv_bfloat16 ly = __float2bfloat16(y - __bfloat162float(hy));
    __nv_bfloat162 h2; h2.x = hx; h2.y = hy;
    __nv_bfloat162 l2; l2.x = lx; l2.y = ly;
    hi = *reinterpret_cast<const uint32_t*>(&h2);
    lo = *reinterpret_cast<const uint32_t*>(&l2);
}

// ---------------------------------------------------------------------------
// fp32 -> (hi, lo) bf16 split for 4 weight matrices in one launch
// ---------------------------------------------------------------------------
__global__ __launch_bounds__(256) void convw4_kernel(
    const float* __restrict__ w0, const float* __restrict__ w1,
    const float* __restrict__ w2, const float* __restrict__ w3)
{
    const int m = blockIdx.y;
    const float* w = (m == 0) ? w0 : (m == 1) ? w1 : (m == 2) ? w2 : w3;
    const int i = blockIdx.x * 256 + threadIdx.x;
    const float v = w[i];
    const __nv_bfloat16 h = __float2bfloat16(v);
    g_Whi[m * Cv * Cv + i] = h;
    g_Wlo[m * Cv * Cv + i] = __float2bfloat16(v - __bfloat162float(h));
}

// ---------------------------------------------------------------------------
// Fused: [b][c][t] fp32 -> [b][t][c] bf16 hi/lo for BOTH x and c.
// grid (T/32, C/32, 2B); z < B: x -> Xhi/Xlo; else c -> Chi/Clo.
// ---------------------------------------------------------------------------
__global__ __launch_bounds__(256) void tconv2_kernel(
    const float* __restrict__ inx, const float* __restrict__ inc)
{
    __shared__ float tile[32][33];
    const int zz = blockIdx.z;
    const int b = (zz < Bv) ? zz : zz - Bv;
    const float* in = (zz < Bv) ? inx : inc;
    __nv_bfloat16* hi = (zz < Bv) ? g_Xhi : g_Chi;
    __nv_bfloat16* lo = (zz < Bv) ? g_Xlo : g_Clo;
    const int c0 = blockIdx.y * 32, t0 = blockIdx.x * 32;
    const int tx = threadIdx.x, ty = threadIdx.y;
    const float* src = in + ((size_t)b * Cv + c0) * Tv + t0;
#pragma unroll
    for (int i = ty; i < 32; i += 8)
        tile[i][tx] = src[(size_t)i * Tv + tx];
    __syncthreads();
#pragma unroll
    for (int i = ty; i < 32; i += 8) {
        const float v = tile[tx][i];
        const size_t o = ((size_t)b * Tv + t0 + i) * Cv + c0 + tx;
        const __nv_bfloat16 h = __float2bfloat16(v);
        hi[o] = h;
        lo[o] = __float2bfloat16(v - __bfloat162float(h));
    }
}

// ---------------------------------------------------------------------------
// mask -> bitmask
// ---------------------------------------------------------------------------
__global__ __launch_bounds__(256) void maskbits_kernel(const float* __restrict__ mask)
{
    const int b = blockIdx.y;
    const int t = blockIdx.x * 8 + (threadIdx.x >> 5);
    const int lane = threadIdx.x & 31;
    const float* row = mask + ((size_t)b * Tv + t) * Tv;
    uint32_t* dst = g_BM + ((size_t)b * Tv + t) * 32;
#pragma unroll 4
    for (int wd = 0; wd < 32; wd++) {
        const float v = row[wd * 32 + lane];
        const uint32_t word = __ballot_sync(0xffffffffu, v != 0.f);
        if (lane == 0) dst[wd] = word;
    }
}

// ---------------------------------------------------------------------------
// HMMA split-bf16 GEMM, cp.async double-buffered pipeline (R10 structure:
// SEPARATE launches per projection — fused QKV measured 2x slower per unit
// work in R12 due to L2 working-set blowup).
// MODE 0: D[t][o] = act[t][:] . W[o][:]^T; out split bf16 [b][t][C] (Q/K)
// MODE 1: D[o][t] = W[o][:] . act[t][:]^T; out split bf16 [b][C][t] (V)
// MODE 2: D[o][t] ... out fp32 [b][C][t] (final projection)
// ---------------------------------------------------------------------------
#define KCH 32
#define SSTR 40
#define GARR (128 * SSTR)
#define GSTAGE (4 * GARR)
#define GEMM_SMEM_BYTES (2 * GSTAGE * 2)

__device__ __forceinline__ void gemm_stage_cp(
    __nv_bfloat16* st, const __nv_bfloat16* pAh, const __nv_bfloat16* pAl,
    const __nv_bfloat16* pBh, const __nv_bfloat16* pBl, int kc0, int tid)
{
    __nv_bfloat16* sAh = st;
    __nv_bfloat16* sAl = st + GARR;
    __nv_bfloat16* sBh = st + 2 * GARR;
    __nv_bfloat16* sBl = st + 3 * GARR;
#pragma unroll
    for (int u = 0; u < 2; u++) {
        const int idx = tid + u * 256;
        const int r = idx >> 2, c8 = (idx & 3) * 8;
        const size_t go = (size_t)r * Cv + kc0 + c8;
        const uint32_t so = (uint32_t)(r * SSTR + c8);
        CP_ASYNC16(s2u(sAh + so), pAh + go);
        CP_ASYNC16(s2u(sAl + so), pAl + go);
        CP_ASYNC16(s2u(sBh + so), pBh + go);
        CP_ASYNC16(s2u(sBl + so), pBl + go);
    }
}

template<int MODE>
__global__ __launch_bounds__(256, 2) void hmma_gemm(
    const __nv_bfloat16* __restrict__ Wh_, const __nv_bfloat16* __restrict__ Wl_,
    const __nv_bfloat16* __restrict__ Acth, const __nv_bfloat16* __restrict__ Actl,
    const float* __restrict__ bias, float scale,
    float* __restrict__ outf,
    __nv_bfloat16* __restrict__ outhi, __nv_bfloat16* __restrict__ outlo)
{
    extern __shared__ __align__(16) __nv_bfloat16 gsm[];

    const int nblk = blockIdx.x * 128, mblk = blockIdx.y * 128, b = blockIdx.z;
    const int tid = threadIdx.x, wid = tid >> 5, lid = tid & 31;
    const int wm = wid >> 2, wn = wid & 3;
    const int m0 = wm * 64, n0 = wn * 32;
    const int g = lid >> 2, tg = lid & 3;

    const __nv_bfloat16 *pAh, *pAl, *pBh, *pBl;
    if (MODE == 0) {
        pAh = Acth + ((size_t)b * Tv + mblk) * Cv;
        pAl = Actl + ((size_t)b * Tv + mblk) * Cv;
        pBh = Wh_ + (size_t)nblk * Cv;
        pBl = Wl_ + (size_t)nblk * Cv;
    } else {
        pAh = Wh_ + (size_t)mblk * Cv;
        pAl = Wl_ + (size_t)mblk * Cv;
        pBh = Acth + ((size_t)b * Tv + nblk) * Cv;
        pBl = Actl + ((size_t)b * Tv + nblk) * Cv;
    }

    float acc[4][4][4];
#pragma unroll
    for (int mi = 0; mi < 4; mi++)
#pragma unroll
        for (int nj = 0; nj < 4; nj++)
#pragma unroll
            for (int r = 0; r < 4; r++) acc[mi][nj][r] = 0.f;

    gemm_stage_cp(gsm, pAh, pAl, pBh, pBl, 0, tid);
    CP_COMMIT();

    for (int kc0 = 0, it = 0; kc0 < Cv; kc0 += KCH, it++) {
        if (kc0 + KCH < Cv) {
            gemm_stage_cp(gsm + ((it + 1) & 1) * GSTAGE, pAh, pAl, pBh, pBl,
                          kc0 + KCH, tid);
            CP_COMMIT();
            CP_WAIT1();
        } else {
            CP_WAIT0();
        }
        __syncthreads();

        const __nv_bfloat16* st = gsm + (it & 1) * GSTAGE;
        const __nv_bfloat16* sAh = st;
        const __nv_bfloat16* sAl = st + GARR;
        const __nv_bfloat16* sBh = st + 2 * GARR;
        const __nv_bfloat16* sBl = st + 3 * GARR;

#pragma unroll
        for (int ks = 0; ks < KCH; ks += 16) {
            const int kk = ks + tg * 2;
            uint32_t ah[4][4], al[4][4], bh[4][2], bl[4][2];
#pragma unroll
            for (int mi = 0; mi < 4; mi++) {
                const int row = m0 + mi * 16 + g;
                ah[mi][0] = ldb32(&sAh[row * SSTR + kk]);
                ah[mi][1] = ldb32(&sAh[(row + 8) * SSTR + kk]);
                ah[mi][2] = ldb32(&sAh[row * SSTR + kk + 8]);
                ah[mi][3] = ldb32(&sAh[(row + 8) * SSTR + kk + 8]);
                al[mi][0] = ldb32(&sAl[row * SSTR + kk]);
                al[mi][1] = ldb32(&sAl[(row + 8) * SSTR + kk]);
                al[mi][2] = ldb32(&sAl[row * SSTR + kk + 8]);
                al[mi][3] = ldb32(&sAl[(row + 8) * SSTR + kk + 8]);
            }
#pragma unroll
            for (int nj = 0; nj < 4; nj++) {
                const int col = n0 + nj * 8 + g;
                bh[nj][0] = ldb32(&sBh[col * SSTR + kk]);
                bh[nj][1] = ldb32(&sBh[col * SSTR + kk + 8]);
                bl[nj][0] = ldb32(&sBl[col * SSTR + kk]);
                bl[nj][1] = ldb32(&sBl[col * SSTR + kk + 8]);
            }
#pragma unroll
            for (int mi = 0; mi < 4; mi++)
#pragma unroll
                for (int nj = 0; nj < 4; nj++) {
                    MMA16816(acc[mi][nj], ah[mi], bh[nj]);
                    MMA16816(acc[mi][nj], ah[mi], bl[nj]);
                    MMA16816(acc[mi][nj], al[mi], bh[nj]);
                }
        }
        __syncthreads();
    }

    // ---- epilogues ----
    if (MODE == 0) {
#pragma unroll
        for (int mi = 0; mi < 4; mi++) {
            const int t0r = mblk + m0 + mi * 16 + g;
#pragma unroll
            for (int nj = 0; nj < 4; nj++) {
                const int o = nblk + n0 + nj * 8 + tg * 2;
                const float b0 = bias[o], b1 = bias[o + 1];
                uint32_t hw, lw;
                pack_pair((acc[mi][nj][0] + b0) * scale, (acc[mi][nj][1] + b1) * scale, hw, lw);
                const size_t a0 = ((size_t)b * Tv + t0r) * Cv + o;
                *reinterpret_cast<uint32_t*>(&outhi[a0]) = hw;
                *reinterpret_cast<uint32_t*>(&outlo[a0]) = lw;
                pack_pair((acc[mi][nj][2] + b0) * scale, (acc[mi][nj][3] + b1) * scale, hw, lw);
                const size_t a1 = ((size_t)b * Tv + t0r + 8) * Cv + o;
                *reinterpret_cast<uint32_t*>(&outhi[a1]) = hw;
                *reinterpret_cast<uint32_t*>(&outlo[a1]) = lw;
            }
        }
    } else if (MODE == 1) {
#pragma unroll
        for (int mi = 0; mi < 4; mi++) {
            const int o = mblk + m0 + mi * 16 + g;
            const float b0 = bias[o], b1 = bias[o + 8];
#pragma unroll
            for (int nj = 0; nj < 4; nj++) {
                const int t = nblk + n0 + nj * 8 + tg * 2;
                uint32_t hw, lw;
                pack_pair(acc[mi][nj][0] + b0, acc[mi][nj][1] + b0, hw, lw);
                const size_t a0 = ((size_t)b * Cv + o) * Tv + t;
                *reinterpret_cast<uint32_t*>(&outhi[a0]) = hw;
                *reinterpret_cast<uint32_t*>(&outlo[a0]) = lw;
                pack_pair(acc[mi][nj][2] + b1, acc[mi][nj][3] + b1, hw, lw);
                const size_t a1 = ((size_t)b * Cv + o + 8) * Tv + t;
                *reinterpret_cast<uint32_t*>(&outhi[a1]) = hw;
                *reinterpret_cast<uint32_t*>(&outlo[a1]) = lw;
            }
        }
    } else {
#pragma unroll
        for (int mi = 0; mi < 4; mi++) {
            const int o = mblk + m0 + mi * 16 + g;
            const float b0 = bias[o], b1 = bias[o + 8];
#pragma unroll
            for (int nj = 0; nj < 4; nj++) {
                const int t = nblk + n0 + nj * 8 + tg * 2;
                float2 v0, v1;
                v0.x = acc[mi][nj][0] + b0;
                v0.y = acc[mi][nj][1] + b0;
                v1.x = acc[mi][nj][2] + b1;
                v1.y = acc[mi][nj][3] + b1;
                *reinterpret_cast<float2*>(&outf[((size_t)b * Cv + o) * Tv + t]) = v0;
                *reinterpret_cast<float2*>(&outf[((size_t)b * Cv + o + 8) * Tv + t]) = v1;
            }
        }
    }
}

// ---------------------------------------------------------------------------
// HMMA banded flash attention. Fixed-shift softmax (shift -20 folded into
// sBias; exact by shift invariance — logits bounded ~|10|). grid (T/128,H,B),
// block 256, 2 CTAs/SM, per-warp chunk skip.
// ---------------------------------------------------------------------------
#define QSTR 72

#define OFF_QH 0
#define OFF_QL (128 * QSTR)
#define OFF_KH (2 * 128 * QSTR)
#define OFF_KL (2 * 128 * QSTR + 64 * QSTR)
#define OFF_VH (2 * 128 * QSTR + 2 * 64 * QSTR)
#define OFF_VL (2 * 128 * QSTR + 3 * 64 * QSTR)
#define BF16_ELEMS (2 * 128 * QSTR + 4 * 64 * QSTR)
#define F_RK   0
#define F_BIAS (128 * 12)
#define F_EV   (128 * 12 + 516)
#define F_EK   (128 * 12 + 516 + 576)
#define F_PD   (128 * 12 + 516 + 2 * 576)
#define F_TOTAL (2 * 128 * 12 + 516 + 2 * 576)
#define ATTN_SMEM_BYTES (BF16_ELEMS * 2 + F_TOTAL * 4)
#define SOFTMAX_SHIFT 20.0f

__global__ __launch_bounds__(256, 2) void attn_hmma(
    const float* __restrict__ ek, const float* __restrict__ ev)
{
    extern __shared__ __align__(16) char smem_raw[];
    __nv_bfloat16* sB16 = reinterpret_cast<__nv_bfloat16*>(smem_raw);
    float* sF = reinterpret_cast<float*>(smem_raw + BF16_ELEMS * 2);
    __nv_bfloat16* sQh = sB16 + OFF_QH;
    __nv_bfloat16* sQl = sB16 + OFF_QL;
    __nv_bfloat16* sKh = sB16 + OFF_KH;
    __nv_bfloat16* sKl = sB16 + OFF_KL;
    __nv_bfloat16* sVh = sB16 + OFF_VH;
    __nv_bfloat16* sVl = sB16 + OFF_VL;
    float* sRK   = sF + F_RK;
    float* sBias = sF + F_BIAS;
    float* sEV   = sF + F_EV;
    float* sEK   = sF + F_EK;
    float* sPd   = sF + F_PD;

    const int t0 = blockIdx.x * 128;
    const int h  = blockIdx.y;
    const int b  = blockIdx.z;
    const int tid = threadIdx.x, wid = tid >> 5, lid = tid & 31;
    const int g = lid >> 2, tg = lid & 3;
    const int wloc = wid * 16;

    const __nv_bfloat16* Kh_b = g_Khi + ((size_t)b * Tv) * Cv + h * 64;
    const __nv_bfloat16* Kl_b = g_Klo + ((size_t)b * Tv) * Cv + h * 64;
    const __nv_bfloat16* Vh_b = g_Vhi + ((size_t)b * Cv + h * 64) * Tv;
    const __nv_bfloat16* Vl_b = g_Vlo + ((size_t)b * Cv + h * 64) * Tv;
    const size_t qrow0 = ((size_t)b * Tv + t0) * Cv + h * 64;

    for (int i = tid; i < 1024; i += 256) {
        const int t = i >> 3, seg = (i & 7) * 8;
        *reinterpret_cast<uint4*>(&sQh[t * QSTR + seg]) =
            *reinterpret_cast<const uint4*>(&g_Qhi[qrow0 + (size_t)t * Cv + seg]);
        *reinterpret_cast<uint4*>(&sQl[t * QSTR + seg]) =
            *reinterpret_cast<const uint4*>(&g_Qlo[qrow0 + (size_t)t * Cv + seg]);
    }
    for (int i = tid; i < 513; i += 256)
        sBias[i] = -log1pf(fabsf((float)(i - 256))) - SOFTMAX_SHIFT;
    for (int i = tid; i < 576; i += 256) { sEK[i] = ek[i]; sEV[i] = ev[i]; }
    __syncthreads();

    for (int i = tid; i < 1152; i += 256) {
        const int tl = i & 127, dd = i >> 7;
        float s = 0.f;
#pragma unroll 16
        for (int kc = 0; kc < 64; kc++) {
            const float q = __bfloat162float(sQh[tl * QSTR + kc]) +
                            __bfloat162float(sQl[tl * QSTR + kc]);
            s += q * sEK[dd * 64 + kc];
        }
        sRK[tl * 12 + dd] = s;
    }

    float l0 = 0.f, l1 = 0.f;
    float O[8][4];
#pragma unroll
    for (int nt = 0; nt < 8; nt++)
#pragma unroll
        for (int r = 0; r < 4; r++) O[nt][r] = 0.f;

    const int s_lo = max(0, t0 - 256);
    const int s_hi = min(Tv, t0 + 128 + 256);

    for (int s0 = s_lo; s0 < s_hi; s0 += 64) {
        const bool window = (s0 >= t0 - 64) && (s0 <= t0 + 128);
        const bool active = (s0 + 63 >= t0 + wloc - 256) && (s0 <= t0 + wloc + 15 + 256);
        __syncthreads();
        if (window) {
            for (int i = tid; i < 1536; i += 256) sPd[i] = 0.f;
        }
#pragma unroll
        for (int u = 0; u < 2; u++) {
            const int idx = tid + u * 256;
            const int fr = idx >> 3, fseg = (idx & 7) * 8;
            *reinterpret_cast<uint4*>(&sKh[fr * QSTR + fseg]) =
                *reinterpret_cast<const uint4*>(&Kh_b[(size_t)(s0 + fr) * Cv + fseg]);
            *reinterpret_cast<uint4*>(&sKl[fr * QSTR + fseg]) =
                *reinterpret_cast<const uint4*>(&Kl_b[(size_t)(s0 + fr) * Cv + fseg]);
            *reinterpret_cast<uint4*>(&sVh[fr * QSTR + fseg]) =
                *reinterpret_cast<const uint4*>(&Vh_b[(size_t)fr * Tv + s0 + fseg]);
            *reinterpret_cast<uint4*>(&sVl[fr * QSTR + fseg]) =
                *reinterpret_cast<const uint4*>(&Vl_b[(size_t)fr * Tv + s0 + fseg]);
        }
        __syncthreads();

        if (!active) continue;

        const int w0 = s0 >> 5;
        const int row0 = t0 + wloc + g;
        const uint32_t bA0 = g_BM[((size_t)b * Tv + row0) * 32 + w0];
        const uint32_t bA1 = g_BM[((size_t)b * Tv + row0) * 32 + w0 + 1];
        const uint32_t bB0 = g_BM[((size_t)b * Tv + row0 + 8) * 32 + w0];
        const uint32_t bB1 = g_BM[((size_t)b * Tv + row0 + 8) * 32 + w0 + 1];

        // ---- S = Q K^T ----
        float S[8][4];
#pragma unroll
        for (int nt = 0; nt < 8; nt++)
#pragma unroll
            for (int r = 0; r < 4; r++) S[nt][r] = 0.f;

#pragma unroll
        for (int ks = 0; ks < 4; ks++) {
            const int qr = (wloc + g) * QSTR + ks * 16 + tg * 2;
            uint32_t aqh[4], aql[4];
            aqh[0] = ldb32(&sQh[qr]);
            aqh[1] = ldb32(&sQh[qr + 8 * QSTR]);
            aqh[2] = ldb32(&sQh[qr + 8]);
            aqh[3] = ldb32(&sQh[qr + 8 * QSTR + 8]);
            aql[0] = ldb32(&sQl[qr]);
            aql[1] = ldb32(&sQl[qr + 8 * QSTR]);
            aql[2] = ldb32(&sQl[qr + 8]);
            aql[3] = ldb32(&sQl[qr + 8 * QSTR + 8]);
#pragma unroll
            for (int nt = 0; nt < 8; nt++) {
                const int kr = (nt * 8 + g) * QSTR + ks * 16 + tg * 2;
                uint32_t bh[2], bl[2];
                bh[0] = ldb32(&sKh[kr]);
                bh[1] = ldb32(&sKh[kr + 8]);
                bl[0] = ldb32(&sKl[kr]);
                bl[1] = ldb32(&sKl[kr + 8]);
                MMA16816(S[nt], aqh, bh);
                MMA16816(S[nt], aqh, bl);
                MMA16816(S[nt], aql, bh);
            }
        }

        // ---- biases + band + mask + exp (fixed shift), accumulate l ----
        float rs0 = 0.f, rs1 = 0.f;
#pragma unroll
        for (int nt = 0; nt < 8; nt++) {
#pragma unroll
            for (int r = 0; r < 4; r++) {
                const int tlr = wloc + g + ((r >> 1) << 3);
                const int t = t0 + tlr;
                const int si = nt * 8 + tg * 2 + (r & 1);
                const int s = s0 + si;
                const int d = s - t;
                float v = S[nt][r];
                if (d >= -256 && d <= 256) {
                    v += sBias[d + 256];
                    if (d >= -4 && d <= 4) v += sRK[tlr * 12 + d + 4];
                    const uint32_t wv = (r >> 1) ? ((si >= 32) ? bB1 : bB0)
                                                 : ((si >= 32) ? bA1 : bA0);
                    if (!((wv >> (si & 31)) & 1u)) v = -2e30f;
                } else {
                    v = -2e30f;
                }
                const float p = __expf(v);
                S[nt][r] = p;
                if (r < 2) rs0 += p; else rs1 += p;
            }
        }
        rs0 += __shfl_xor_sync(0xffffffffu, rs0, 1);
        rs0 += __shfl_xor_sync(0xffffffffu, rs0, 2);
        rs1 += __shfl_xor_sync(0xffffffffu, rs1, 1);
        rs1 += __shfl_xor_sync(0xffffffffu, rs1, 2);
        l0 += rs0; l1 += rs1;

        // stash diagonal p's for rel-value stencil (sPd rows warp-exclusive)
        if (window) {
#pragma unroll
            for (int nt = 0; nt < 8; nt++) {
#pragma unroll
                for (int r = 0; r < 4; r++) {
                    const int tlr = wloc + g + ((r >> 1) << 3);
                    const int d = (s0 + nt * 8 + tg * 2 + (r & 1)) - (t0 + tlr);
                    if (d >= -4 && d <= 4) sPd[tlr * 12 + d + 4] = S[nt][r];
                }
            }
        }

        // ---- O += P V ----
#pragma unroll
        for (int ks = 0; ks < 4; ks++) {
            uint32_t aph[4], apl[4];
            pack_pair(S[2 * ks][0],     S[2 * ks][1],     aph[0], apl[0]);
            pack_pair(S[2 * ks][2],     S[2 * ks][3],     aph[1], apl[1]);
            pack_pair(S[2 * ks + 1][0], S[2 * ks + 1][1], aph[2], apl[2]);
            pack_pair(S[2 * ks + 1][2], S[2 * ks + 1][3], aph[3], apl[3]);
#pragma unroll
            for (int nt = 0; nt < 8; nt++) {
                const int vr = (nt * 8 + g) * QSTR + ks * 16 + tg * 2;
                uint32_t bh[2], bl[2];
                bh[0] = ldb32(&sVh[vr]);
                bh[1] = ldb32(&sVh[vr + 8]);
                bl[0] = ldb32(&sVl[vr]);
                bl[1] = ldb32(&sVl[vr + 8]);
                MMA16816(O[nt], aph, bh);
                MMA16816(O[nt], aph, bl);
                MMA16816(O[nt], apl, bh);
            }
        }

        // ---- rel-value 9-tap stencil (same-warp rows) ----
        if (window) {
            __syncwarp();
#pragma unroll
            for (int rh = 0; rh < 2; rh++) {
                const int tlr = wloc + g + rh * 8;
#pragma unroll
                for (int dd = 0; dd < 9; dd++) {
                    const float p = sPd[tlr * 12 + dd];
                    if (p != 0.f) {
#pragma unroll
                        for (int nt = 0; nt < 8; nt++) {
                            O[nt][2 * rh]     += p * sEV[dd * 64 + nt * 8 + tg * 2];
                            O[nt][2 * rh + 1] += p * sEV[dd * 64 + nt * 8 + tg * 2 + 1];
                        }
                    }
                }
            }
        }
    }

    // ---- finalize ----
    const float inv0 = 1.f / l0, inv1 = 1.f / l1;
    const size_t out0 = ((size_t)b * Tv + t0 + wloc + g) * Cv + h * 64;
    const size_t out1 = out0 + 8 * Cv;
#pragma unroll
    for (int nt = 0; nt < 8; nt++) {
        const int kc = nt * 8 + tg * 2;
        uint32_t hw, lw;
        pack_pair(O[nt][0] * inv0, O[nt][1] * inv0, hw, lw);
        *reinterpret_cast<uint32_t*>(&g_Xhi[out0 + kc]) = hw;
        *reinterpret_cast<uint32_t*>(&g_Xlo[out0 + kc]) = lw;
        pack_pair(O[nt][2] * inv1, O[nt][3] * inv1, hw, lw);
        *reinterpret_cast<uint32_t*>(&g_Xhi[out1 + kc]) = hw;
        *reinterpret_cast<uint32_t*>(&g_Xlo[out1 + kc]) = lw;
    }
}

// ---------------------------------------------------------------------------

extern "C" void kernel_launch(void* const* d_in, const int* in_sizes, int n_in,
                              void* d_out, int out_size)
{
    const float* x    = (const float*)d_in[0];
    const float* c    = (const float*)d_in[1];
    const float* mask = (const float*)d_in[2];
    const float* Wq   = (const float*)d_in[3];
    const float* bq   = (const float*)d_in[4];
    const float* Wk   = (const float*)d_in[5];
    const float* bk   = (const float*)d_in[6];
    const float* Wv   = (const float*)d_in[7];
    const float* bv   = (const float*)d_in[8];
    const float* Wo   = (const float*)d_in[9];
    const float* bo   = (const float*)d_in[10];
    const float* ek   = (const float*)d_in[11];
    const float* ev   = (const float*)d_in[12];
    float* out = (float*)d_out;

    __nv_bfloat16 *whi, *wlo, *xhi, *xlo, *chi, *clo, *qhi, *qlo, *khi, *klo, *vhi, *vlo;
    cudaGetSymbolAddress((void**)&whi, g_Whi);
    cudaGetSymbolAddress((void**)&wlo, g_Wlo);
    cudaGetSymbolAddress((void**)&xhi, g_Xhi);
    cudaGetSymbolAddress((void**)&xlo, g_Xlo);
    cudaGetSymbolAddress((void**)&chi, g_Chi);
    cudaGetSymbolAddress((void**)&clo, g_Clo);
    cudaGetSymbolAddress((void**)&qhi, g_Qhi);
    cudaGetSymbolAddress((void**)&qlo, g_Qlo);
    cudaGetSymbolAddress((void**)&khi, g_Khi);
    cudaGetSymbolAddress((void**)&klo, g_Klo);
    cudaGetSymbolAddress((void**)&vhi, g_Vhi);
    cudaGetSymbolAddress((void**)&vlo, g_Vlo);

    cudaFuncSetAttribute(attn_hmma, cudaFuncAttributeMaxDynamicSharedMemorySize,
                         ATTN_SMEM_BYTES);
    cudaFuncSetAttribute(hmma_gemm<0>, cudaFuncAttributeMaxDynamicSharedMemorySize,
                         GEMM_SMEM_BYTES);
    cudaFuncSetAttribute(hmma_gemm<1>, cudaFuncAttributeMaxDynamicSharedMemorySize,
                         GEMM_SMEM_BYTES);
    cudaFuncSetAttribute(hmma_gemm<2>, cudaFuncAttributeMaxDynamicSharedMemorySize,
                         GEMM_SMEM_BYTES);

    const int WSZ = Cv * Cv;

    // pre-passes
    dim3 wg(WSZ / 256, 4);
    convw4_kernel<<<wg, 256>>>(Wq, Wk, Wv, Wo);
    dim3 tg(Tv / 32, Cv / 32, 2 * Bv), tb(32, 8);
    tconv2_kernel<<<tg, tb>>>(x, c);
    maskbits_kernel<<<dim3(Tv / 8, Bv), 256>>>(mask);

    // projections: SEPARATE launches (L2 weight reuse per launch)
    hmma_gemm<0><<<dim3(Cv / 128, Tv / 128, Bv), 256, GEMM_SMEM_BYTES>>>(
        whi + 0 * WSZ, wlo + 0 * WSZ, xhi, xlo, bq, 0.125f, nullptr, qhi, qlo);
    hmma_gemm<0><<<dim3(Cv / 128, Tv / 128, Bv), 256, GEMM_SMEM_BYTES>>>(
        whi + 1 * WSZ, wlo + 1 * WSZ, chi, clo, bk, 1.0f, nullptr, khi, klo);
    hmma_gemm<1><<<dim3(Tv / 128, Cv / 128, Bv), 256, GEMM_SMEM_BYTES>>>(
        whi + 2 * WSZ, wlo + 2 * WSZ, chi, clo, bv, 1.0f, nullptr, vhi, vlo);

    // attention (writes split output into g_Xhi/g_Xlo)
    attn_hmma<<<dim3(Tv / 128, Hh, Bv), 256, ATTN_SMEM_BYTES>>>(ek, ev);

    // final projection (fp32 output)
    hmma_gemm<2><<<dim3(Tv / 128, Cv / 128, Bv), 256, GEMM_SMEM_BYTES>>>(
        whi + 3 * WSZ, wlo + 3 * WSZ, xhi, xlo, bo, 1.0f, out, nullptr, nullptr);
}

// round 14
// speedup vs baseline: 1.4774x; 1.0077x over previous
#include <cuda_runtime.h>
#include <cuda_bf16.h>
#include <math.h>
#include <stdint.h>

#define Bv 8
#define Cv 512
#define Tv 1024
#define Hh 8
#define KCv 64

// ---------------------------------------------------------------------------
// Scratch (allocation-free rule: __device__ globals)
// ---------------------------------------------------------------------------
__device__ __nv_bfloat16 g_Whi[4 * Cv * Cv];
__device__ __nv_bfloat16 g_Wlo[4 * Cv * Cv];
__device__ __nv_bfloat16 g_Xhi[Bv * Tv * Cv];   // x^T split; later attention output
__device__ __nv_bfloat16 g_Xlo[Bv * Tv * Cv];
__device__ __nv_bfloat16 g_Chi[Bv * Tv * Cv];   // c^T split
__device__ __nv_bfloat16 g_Clo[Bv * Tv * Cv];
__device__ __nv_bfloat16 g_Qhi[Bv * Tv * Cv];   // Q split, [b][t][C], pre-scaled
__device__ __nv_bfloat16 g_Qlo[Bv * Tv * Cv];
__device__ __nv_bfloat16 g_Khi[Bv * Tv * Cv];   // K split, [b][t][C]
__device__ __nv_bfloat16 g_Klo[Bv * Tv * Cv];
__device__ __nv_bfloat16 g_Vhi[Bv * Cv * Tv];   // V split, [b][C][t]
__device__ __nv_bfloat16 g_Vlo[Bv * Cv * Tv];
__device__ uint32_t      g_BM[Bv * Tv * 32];    // mask bitmask

// ---------------------------------------------------------------------------
#define MMA16816(d, a, b) \
    asm volatile("mma.sync.aligned.m16n8k16.row.col.f32.bf16.bf16.f32 " \
        "{%0,%1,%2,%3}, {%4,%5,%6,%7}, {%8,%9}, {%0,%1,%2,%3};" \
        : "+f"((d)[0]), "+f"((d)[1]), "+f"((d)[2]), "+f"((d)[3]) \
        : "r"((a)[0]), "r"((a)[1]), "r"((a)[2]), "r"((a)[3]), \
          "r"((b)[0]), "r"((b)[1]))

#define CP_ASYNC16(saddr, gptr) \
    asm volatile("cp.async.cg.shared.global [%0], [%1], 16;" \
                 :: "r"(saddr), "l"(gptr) : "memory")
#define CP_COMMIT() asm volatile("cp.async.commit_group;" ::: "memory")
#define CP_WAIT1()  asm volatile("cp.async.wait_group 1;" ::: "memory")
#define CP_WAIT0()  asm volatile("cp.async.wait_group 0;" ::: "memory")

__device__ __forceinline__ uint32_t ldb32(const __nv_bfloat16* p) {
    return *reinterpret_cast<const uint32_t*>(p);
}
__device__ __forceinline__ uint32_t s2u(const void* p) {
    return (uint32_t)__cvta_generic_to_shared(p);
}
__device__ __forceinline__ void pack_pair(float x, float y, uint32_t& hi, uint32_t& lo) {
    const __nv_bfloat16 hx = __float2bfloat16(x), hy = __float2bfloat16(y);
    const __nv_bfloat16 lx = __float2bfloat16(x - __bfloat162float(hx));
    const __nv_bfloat16 ly = __float2bfloat16(y - __bfloat162float(hy));
    __nv_bfloat162 h2; h2.x = hx; h2.y = hy;
    __nv_bfloat162 l2; l2.x = lx; l2.y = ly;
    hi = *reinterpret_cast<const uint32_t*>(&h2);
    lo = *reinterpret_cast<const uint32_t*>(&l2);
}

// ---------------------------------------------------------------------------
// fp32 -> (hi, lo) bf16 split for 4 weight matrices in one launch
// ---------------------------------------------------------------------------
__global__ __launch_bounds__(256) void convw4_kernel(
    const float* __restrict__ w0, const float* __restrict__ w1,
    const float* __restrict__ w2, const float* __restrict__ w3)
{
    const int m = blockIdx.y;
    const float* w = (m == 0) ? w0 : (m == 1) ? w1 : (m == 2) ? w2 : w3;
    const int i = blockIdx.x * 256 + threadIdx.x;
    const float v = w[i];
    const __nv_bfloat16 h = __float2bfloat16(v);
    g_Whi[m * Cv * Cv + i] = h;
    g_Wlo[m * Cv * Cv + i] = __float2bfloat16(v - __bfloat162float(h));
}

// ---------------------------------------------------------------------------
// Fused: [b][c][t] fp32 -> [b][t][c] bf16 hi/lo for BOTH x and c.
// ---------------------------------------------------------------------------
__global__ __launch_bounds__(256) void tconv2_kernel(
    const float* __restrict__ inx, const float* __restrict__ inc)
{
    __shared__ float tile[32][33];
    const int zz = blockIdx.z;
    const int b = (zz < Bv) ? zz : zz - Bv;
    const float* in = (zz < Bv) ? inx : inc;
    __nv_bfloat16* hi = (zz < Bv) ? g_Xhi : g_Chi;
    __nv_bfloat16* lo = (zz < Bv) ? g_Xlo : g_Clo;
    const int c0 = blockIdx.y * 32, t0 = blockIdx.x * 32;
    const int tx = threadIdx.x, ty = threadIdx.y;
    const float* src = in + ((size_t)b * Cv + c0) * Tv + t0;
#pragma unroll
    for (int i = ty; i < 32; i += 8)
        tile[i][tx] = src[(size_t)i * Tv + tx];
    __syncthreads();
#pragma unroll
    for (int i = ty; i < 32; i += 8) {
        const float v = tile[tx][i];
        const size_t o = ((size_t)b * Tv + t0 + i) * Cv + c0 + tx;
        const __nv_bfloat16 h = __float2bfloat16(v);
        hi[o] = h;
        lo[o] = __float2bfloat16(v - __bfloat162float(h));
    }
}

// ---------------------------------------------------------------------------
// mask -> bitmask
// ---------------------------------------------------------------------------
__global__ __launch_bounds__(256) void maskbits_kernel(const float* __restrict__ mask)
{
    const int b = blockIdx.y;
    const int t = blockIdx.x * 8 + (threadIdx.x >> 5);
    const int lane = threadIdx.x & 31;
    const float* row = mask + ((size_t)b * Tv + t) * Tv;
    uint32_t* dst = g_BM + ((size_t)b * Tv + t) * 32;
#pragma unroll 4
    for (int wd = 0; wd < 32; wd++) {
        const float v = row[wd * 32 + lane];
        const uint32_t word = __ballot_sync(0xffffffffu, v != 0.f);
        if (lane == 0) dst[wd] = word;
    }
}

// ---------------------------------------------------------------------------
// HMMA split-bf16 GEMM, cp.async double-buffered pipeline (separate launches).
// ---------------------------------------------------------------------------
#define KCH 32
#define SSTR 40
#define GARR (128 * SSTR)
#define GSTAGE (4 * GARR)
#define GEMM_SMEM_BYTES (2 * GSTAGE * 2)

__device__ __forceinline__ void gemm_stage_cp(
    __nv_bfloat16* st, const __nv_bfloat16* pAh, const __nv_bfloat16* pAl,
    const __nv_bfloat16* pBh, const __nv_bfloat16* pBl, int kc0, int tid)
{
    __nv_bfloat16* sAh = st;
    __nv_bfloat16* sAl = st + GARR;
    __nv_bfloat16* sBh = st + 2 * GARR;
    __nv_bfloat16* sBl = st + 3 * GARR;
#pragma unroll
    for (int u = 0; u < 2; u++) {
        const int idx = tid + u * 256;
        const int r = idx >> 2, c8 = (idx & 3) * 8;
        const size_t go = (size_t)r * Cv + kc0 + c8;
        const uint32_t so = (uint32_t)(r * SSTR + c8);
        CP_ASYNC16(s2u(sAh + so), pAh + go);
        CP_ASYNC16(s2u(sAl + so), pAl + go);
        CP_ASYNC16(s2u(sBh + so), pBh + go);
        CP_ASYNC16(s2u(sBl + so), pBl + go);
    }
}

template<int MODE>
__global__ __launch_bounds__(256, 2) void hmma_gemm(
    const __nv_bfloat16* __restrict__ Wh_, const __nv_bfloat16* __restrict__ Wl_,
    const __nv_bfloat16* __restrict__ Acth, const __nv_bfloat16* __restrict__ Actl,
    const float* __restrict__ bias, float scale,
    float* __restrict__ outf,
    __nv_bfloat16* __restrict__ outhi, __nv_bfloat16* __restrict__ outlo)
{
    extern __shared__ __align__(16) __nv_bfloat16 gsm[];

    const int nblk = blockIdx.x * 128, mblk = blockIdx.y * 128, b = blockIdx.z;
    const int tid = threadIdx.x, wid = tid >> 5, lid = tid & 31;
    const int wm = wid >> 2, wn = wid & 3;
    const int m0 = wm * 64, n0 = wn * 32;
    const int g = lid >> 2, tg = lid & 3;

    const __nv_bfloat16 *pAh, *pAl, *pBh, *pBl;
    if (MODE == 0) {
        pAh = Acth + ((size_t)b * Tv + mblk) * Cv;
        pAl = Actl + ((size_t)b * Tv + mblk) * Cv;
        pBh = Wh_ + (size_t)nblk * Cv;
        pBl = Wl_ + (size_t)nblk * Cv;
    } else {
        pAh = Wh_ + (size_t)mblk * Cv;
        pAl = Wl_ + (size_t)mblk * Cv;
        pBh = Acth + ((size_t)b * Tv + nblk) * Cv;
        pBl = Actl + ((size_t)b * Tv + nblk) * Cv;
    }

    float acc[4][4][4];
#pragma unroll
    for (int mi = 0; mi < 4; mi++)
#pragma unroll
        for (int nj = 0; nj < 4; nj++)
#pragma unroll
            for (int r = 0; r < 4; r++) acc[mi][nj][r] = 0.f;

    gemm_stage_cp(gsm, pAh, pAl, pBh, pBl, 0, tid);
    CP_COMMIT();

    for (int kc0 = 0, it = 0; kc0 < Cv; kc0 += KCH, it++) {
        if (kc0 + KCH < Cv) {
            gemm_stage_cp(gsm + ((it + 1) & 1) * GSTAGE, pAh, pAl, pBh, pBl,
                          kc0 + KCH, tid);
            CP_COMMIT();
            CP_WAIT1();
        } else {
            CP_WAIT0();
        }
        __syncthreads();

        const __nv_bfloat16* st = gsm + (it & 1) * GSTAGE;
        const __nv_bfloat16* sAh = st;
        const __nv_bfloat16* sAl = st + GARR;
        const __nv_bfloat16* sBh = st + 2 * GARR;
        const __nv_bfloat16* sBl = st + 3 * GARR;

#pragma unroll
        for (int ks = 0; ks < KCH; ks += 16) {
            const int kk = ks + tg * 2;
            uint32_t ah[4][4], al[4][4], bh[4][2], bl[4][2];
#pragma unroll
            for (int mi = 0; mi < 4; mi++) {
                const int row = m0 + mi * 16 + g;
                ah[mi][0] = ldb32(&sAh[row * SSTR + kk]);
                ah[mi][1] = ldb32(&sAh[(row + 8) * SSTR + kk]);
                ah[mi][2] = ldb32(&sAh[row * SSTR + kk + 8]);
                ah[mi][3] = ldb32(&sAh[(row + 8) * SSTR + kk + 8]);
                al[mi][0] = ldb32(&sAl[row * SSTR + kk]);
                al[mi][1] = ldb32(&sAl[(row + 8) * SSTR + kk]);
                al[mi][2] = ldb32(&sAl[row * SSTR + kk + 8]);
                al[mi][3] = ldb32(&sAl[(row + 8) * SSTR + kk + 8]);
            }
#pragma unroll
            for (int nj = 0; nj < 4; nj++) {
                const int col = n0 + nj * 8 + g;
                bh[nj][0] = ldb32(&sBh[col * SSTR + kk]);
                bh[nj][1] = ldb32(&sBh[col * SSTR + kk + 8]);
                bl[nj][0] = ldb32(&sBl[col * SSTR + kk]);
                bl[nj][1] = ldb32(&sBl[col * SSTR + kk + 8]);
            }
#pragma unroll
            for (int mi = 0; mi < 4; mi++)
#pragma unroll
                for (int nj = 0; nj < 4; nj++) {
                    MMA16816(acc[mi][nj], ah[mi], bh[nj]);
                    MMA16816(acc[mi][nj], ah[mi], bl[nj]);
                    MMA16816(acc[mi][nj], al[mi], bh[nj]);
                }
        }
        __syncthreads();
    }

    // ---- epilogues ----
    if (MODE == 0) {
#pragma unroll
        for (int mi = 0; mi < 4; mi++) {
            const int t0r = mblk + m0 + mi * 16 + g;
#pragma unroll
            for (int nj = 0; nj < 4; nj++) {
                const int o = nblk + n0 + nj * 8 + tg * 2;
                const float b0 = bias[o], b1 = bias[o + 1];
                uint32_t hw, lw;
                pack_pair((acc[mi][nj][0] + b0) * scale, (acc[mi][nj][1] + b1) * scale, hw, lw);
                const size_t a0 = ((size_t)b * Tv + t0r) * Cv + o;
                *reinterpret_cast<uint32_t*>(&outhi[a0]) = hw;
                *reinterpret_cast<uint32_t*>(&outlo[a0]) = lw;
                pack_pair((acc[mi][nj][2] + b0) * scale, (acc[mi][nj][3] + b1) * scale, hw, lw);
                const size_t a1 = ((size_t)b * Tv + t0r + 8) * Cv + o;
                *reinterpret_cast<uint32_t*>(&outhi[a1]) = hw;
                *reinterpret_cast<uint32_t*>(&outlo[a1]) = lw;
            }
        }
    } else if (MODE == 1) {
#pragma unroll
        for (int mi = 0; mi < 4; mi++) {
            const int o = mblk + m0 + mi * 16 + g;
            const float b0 = bias[o], b1 = bias[o + 8];
#pragma unroll
            for (int nj = 0; nj < 4; nj++) {
                const int t = nblk + n0 + nj * 8 + tg * 2;
                uint32_t hw, lw;
                pack_pair(acc[mi][nj][0] + b0, acc[mi][nj][1] + b0, hw, lw);
                const size_t a0 = ((size_t)b * Cv + o) * Tv + t;
                *reinterpret_cast<uint32_t*>(&outhi[a0]) = hw;
                *reinterpret_cast<uint32_t*>(&outlo[a0]) = lw;
                pack_pair(acc[mi][nj][2] + b1, acc[mi][nj][3] + b1, hw, lw);
                const size_t a1 = ((size_t)b * Cv + o + 8) * Tv + t;
                *reinterpret_cast<uint32_t*>(&outhi[a1]) = hw;
                *reinterpret_cast<uint32_t*>(&outlo[a1]) = lw;
            }
        }
    } else {
#pragma unroll
        for (int mi = 0; mi < 4; mi++) {
            const int o = mblk + m0 + mi * 16 + g;
            const float b0 = bias[o], b1 = bias[o + 8];
#pragma unroll
            for (int nj = 0; nj < 4; nj++) {
                const int t = nblk + n0 + nj * 8 + tg * 2;
                float2 v0, v1;
                v0.x = acc[mi][nj][0] + b0;
                v0.y = acc[mi][nj][1] + b0;
                v1.x = acc[mi][nj][2] + b1;
                v1.y = acc[mi][nj][3] + b1;
                *reinterpret_cast<float2*>(&outf[((size_t)b * Cv + o) * Tv + t]) = v0;
                *reinterpret_cast<float2*>(&outf[((size_t)b * Cv + o + 8) * Tv + t]) = v1;
            }
        }
    }
}

// ---------------------------------------------------------------------------
// HMMA banded flash attention. Fixed-shift softmax. Phase-split cp.async
// pipeline: V(i) fills during QK^T(i); K(i+1) fills during PV(i). Commit
// order K0,V0,K1,V1,... -> wait_group 1 always exposes the needed buffer
// (wait_group 0 on the final chunk where no new group was committed).
// grid (T/128, H, B), block 256, 2 CTAs/SM, per-warp chunk skip.
// ---------------------------------------------------------------------------
#define QSTR 72

#define OFF_QH 0
#define OFF_QL (128 * QSTR)
#define OFF_KH (2 * 128 * QSTR)
#define OFF_KL (2 * 128 * QSTR + 64 * QSTR)
#define OFF_VH (2 * 128 * QSTR + 2 * 64 * QSTR)
#define OFF_VL (2 * 128 * QSTR + 3 * 64 * QSTR)
#define BF16_ELEMS (2 * 128 * QSTR + 4 * 64 * QSTR)
#define F_RK   0
#define F_BIAS (128 * 12)
#define F_EV   (128 * 12 + 516)
#define F_EK   (128 * 12 + 516 + 576)
#define F_PD   (128 * 12 + 516 + 2 * 576)
#define F_TOTAL (2 * 128 * 12 + 516 + 2 * 576)
#define ATTN_SMEM_BYTES (BF16_ELEMS * 2 + F_TOTAL * 4)
#define SOFTMAX_SHIFT 20.0f

__global__ __launch_bounds__(256, 2) void attn_hmma(
    const float* __restrict__ ek, const float* __restrict__ ev)
{
    extern __shared__ __align__(16) char smem_raw[];
    __nv_bfloat16* sB16 = reinterpret_cast<__nv_bfloat16*>(smem_raw);
    float* sF = reinterpret_cast<float*>(smem_raw + BF16_ELEMS * 2);
    __nv_bfloat16* sQh = sB16 + OFF_QH;
    __nv_bfloat16* sQl = sB16 + OFF_QL;
    __nv_bfloat16* sKh = sB16 + OFF_KH;
    __nv_bfloat16* sKl = sB16 + OFF_KL;
    __nv_bfloat16* sVh = sB16 + OFF_VH;
    __nv_bfloat16* sVl = sB16 + OFF_VL;
    float* sRK   = sF + F_RK;
    float* sBias = sF + F_BIAS;
    float* sEV   = sF + F_EV;
    float* sEK   = sF + F_EK;
    float* sPd   = sF + F_PD;

    const int t0 = blockIdx.x * 128;
    const int h  = blockIdx.y;
    const int b  = blockIdx.z;
    const int tid = threadIdx.x, wid = tid >> 5, lid = tid & 31;
    const int g = lid >> 2, tg = lid & 3;
    const int wloc = wid * 16;

    const __nv_bfloat16* Kh_b = g_Khi + ((size_t)b * Tv) * Cv + h * 64;
    const __nv_bfloat16* Kl_b = g_Klo + ((size_t)b * Tv) * Cv + h * 64;
    const __nv_bfloat16* Vh_b = g_Vhi + ((size_t)b * Cv + h * 64) * Tv;
    const __nv_bfloat16* Vl_b = g_Vlo + ((size_t)b * Cv + h * 64) * Tv;
    const size_t qrow0 = ((size_t)b * Tv + t0) * Cv + h * 64;

    // per-thread fill coordinates (2 uint4 per array per thread)
    const int f0 = tid, f1 = tid + 256;
    const int fr0 = f0 >> 3, fs0 = (f0 & 7) * 8;
    const int fr1 = f1 >> 3, fs1 = (f1 & 7) * 8;

    for (int i = tid; i < 1024; i += 256) {
        const int t = i >> 3, seg = (i & 7) * 8;
        *reinterpret_cast<uint4*>(&sQh[t * QSTR + seg]) =
            *reinterpret_cast<const uint4*>(&g_Qhi[qrow0 + (size_t)t * Cv + seg]);
        *reinterpret_cast<uint4*>(&sQl[t * QSTR + seg]) =
            *reinterpret_cast<const uint4*>(&g_Qlo[qrow0 + (size_t)t * Cv + seg]);
    }
    for (int i = tid; i < 513; i += 256)
        sBias[i] = -log1pf(fabsf((float)(i - 256))) - SOFTMAX_SHIFT;
    for (int i = tid; i < 576; i += 256) { sEK[i] = ek[i]; sEV[i] = ev[i]; }

    const int s_lo = max(0, t0 - 256);
    const int s_hi = min(Tv, t0 + 128 + 256);

    // prologue: K(0) group, then V(0) group
    CP_ASYNC16(s2u(&sKh[fr0 * QSTR + fs0]), &Kh_b[(size_t)(s_lo + fr0) * Cv + fs0]);
    CP_ASYNC16(s2u(&sKh[fr1 * QSTR + fs1]), &Kh_b[(size_t)(s_lo + fr1) * Cv + fs1]);
    CP_ASYNC16(s2u(&sKl[fr0 * QSTR + fs0]), &Kl_b[(size_t)(s_lo + fr0) * Cv + fs0]);
    CP_ASYNC16(s2u(&sKl[fr1 * QSTR + fs1]), &Kl_b[(size_t)(s_lo + fr1) * Cv + fs1]);
    CP_COMMIT();
    CP_ASYNC16(s2u(&sVh[fr0 * QSTR + fs0]), &Vh_b[(size_t)fr0 * Tv + s_lo + fs0]);
    CP_ASYNC16(s2u(&sVh[fr1 * QSTR + fs1]), &Vh_b[(size_t)fr1 * Tv + s_lo + fs1]);
    CP_ASYNC16(s2u(&sVl[fr0 * QSTR + fs0]), &Vl_b[(size_t)fr0 * Tv + s_lo + fs0]);
    CP_ASYNC16(s2u(&sVl[fr1 * QSTR + fs1]), &Vl_b[(size_t)fr1 * Tv + s_lo + fs1]);
    CP_COMMIT();

    __syncthreads();  // Q/bias/emb visible

    // sRK[t][d] = sum_kc q[t][kc] * ek[d][kc]
    for (int i = tid; i < 1152; i += 256) {
        const int tl = i & 127, dd = i >> 7;
        float s = 0.f;
#pragma unroll 16
        for (int kc = 0; kc < 64; kc++) {
            const float q = __bfloat162float(sQh[tl * QSTR + kc]) +
                            __bfloat162float(sQl[tl * QSTR + kc]);
            s += q * sEK[dd * 64 + kc];
        }
        sRK[tl * 12 + dd] = s;
    }

    float l0 = 0.f, l1 = 0.f;
    float O[8][4];
#pragma unroll
    for (int nt = 0; nt < 8; nt++)
#pragma unroll
        for (int r = 0; r < 4; r++) O[nt][r] = 0.f;

    for (int s0 = s_lo; s0 < s_hi; s0 += 64) {
        const bool window = (s0 >= t0 - 64) && (s0 <= t0 + 128);
        const bool active = (s0 + 63 >= t0 + wloc - 256) && (s0 <= t0 + wloc + 15 + 256);
        const bool has_next = (s0 + 64 < s_hi);
        const int sn = s0 + 64;

        // ---- phase 1: wait K(i) (pending {K(i),V(i)} -> wait<=1) ----
        CP_WAIT1();
        __syncthreads();   // sync1: K visible; prev stencil done before sPd zero

        if (window) {
            for (int i = tid; i < 1536; i += 256) sPd[i] = 0.f;
        }

        float S[8][4];
        if (active) {
#pragma unroll
            for (int nt = 0; nt < 8; nt++)
#pragma unroll
                for (int r = 0; r < 4; r++) S[nt][r] = 0.f;

#pragma unroll
            for (int ks = 0; ks < 4; ks++) {
                const int qr = (wloc + g) * QSTR + ks * 16 + tg * 2;
                uint32_t aqh[4], aql[4];
                aqh[0] = ldb32(&sQh[qr]);
                aqh[1] = ldb32(&sQh[qr + 8 * QSTR]);
                aqh[2] = ldb32(&sQh[qr + 8]);
                aqh[3] = ldb32(&sQh[qr + 8 * QSTR + 8]);
                aql[0] = ldb32(&sQl[qr]);
                aql[1] = ldb32(&sQl[qr + 8 * QSTR]);
                aql[2] = ldb32(&sQl[qr + 8]);
                aql[3] = ldb32(&sQl[qr + 8 * QSTR + 8]);
#pragma unroll
                for (int nt = 0; nt < 8; nt++) {
                    const int kr = (nt * 8 + g) * QSTR + ks * 16 + tg * 2;
                    uint32_t bh[2], bl[2];
                    bh[0] = ldb32(&sKh[kr]);
                    bh[1] = ldb32(&sKh[kr + 8]);
                    bl[0] = ldb32(&sKl[kr]);
                    bl[1] = ldb32(&sKl[kr + 8]);
                    MMA16816(S[nt], aqh, bh);
                    MMA16816(S[nt], aqh, bl);
                    MMA16816(S[nt], aql, bh);
                }
            }

            // biases + band + mask + exp (fixed shift), accumulate l
            const int w0 = s0 >> 5;
            const int row0 = t0 + wloc + g;
            const uint32_t bA0 = g_BM[((size_t)b * Tv + row0) * 32 + w0];
            const uint32_t bA1 = g_BM[((size_t)b * Tv + row0) * 32 + w0 + 1];
            const uint32_t bB0 = g_BM[((size_t)b * Tv + row0 + 8) * 32 + w0];
            const uint32_t bB1 = g_BM[((size_t)b * Tv + row0 + 8) * 32 + w0 + 1];
            float rs0 = 0.f, rs1 = 0.f;
#pragma unroll
            for (int nt = 0; nt < 8; nt++) {
#pragma unroll
                for (int r = 0; r < 4; r++) {
                    const int tlr = wloc + g + ((r >> 1) << 3);
                    const int t = t0 + tlr;
                    const int si = nt * 8 + tg * 2 + (r & 1);
                    const int s = s0 + si;
                    const int d = s - t;
                    float v = S[nt][r];
                    if (d >= -256 && d <= 256) {
                        v += sBias[d + 256];
                        if (d >= -4 && d <= 4) v += sRK[tlr * 12 + d + 4];
                        const uint32_t wv = (r >> 1) ? ((si >= 32) ? bB1 : bB0)
                                                     : ((si >= 32) ? bA1 : bA0);
                        if (!((wv >> (si & 31)) & 1u)) v = -2e30f;
                    } else {
                        v = -2e30f;
                    }
                    const float p = __expf(v);
                    S[nt][r] = p;
                    if (r < 2) rs0 += p; else rs1 += p;
                }
            }
            rs0 += __shfl_xor_sync(0xffffffffu, rs0, 1);
            rs0 += __shfl_xor_sync(0xffffffffu, rs0, 2);
            rs1 += __shfl_xor_sync(0xffffffffu, rs1, 1);
            rs1 += __shfl_xor_sync(0xffffffffu, rs1, 2);
            l0 += rs0; l1 += rs1;
        }

        __syncthreads();   // sync2: all warps done reading sK; sPd zero done

        // issue K(i+1) fill (overlaps phase 2)
        if (has_next) {
            CP_ASYNC16(s2u(&sKh[fr0 * QSTR + fs0]), &Kh_b[(size_t)(sn + fr0) * Cv + fs0]);
            CP_ASYNC16(s2u(&sKh[fr1 * QSTR + fs1]), &Kh_b[(size_t)(sn + fr1) * Cv + fs1]);
            CP_ASYNC16(s2u(&sKl[fr0 * QSTR + fs0]), &Kl_b[(size_t)(sn + fr0) * Cv + fs0]);
            CP_ASYNC16(s2u(&sKl[fr1 * QSTR + fs1]), &Kl_b[(size_t)(sn + fr1) * Cv + fs1]);
            CP_COMMIT();
            CP_WAIT1();    // pending {V(i), K(i+1)} -> V(i) done
        } else {
            CP_WAIT0();    // only V(i) pending
        }
        __syncthreads();   // sync3: V visible

        // ---- phase 2: stash + PV + stencil ----
        if (active) {
            if (window) {
#pragma unroll
                for (int nt = 0; nt < 8; nt++) {
#pragma unroll
                    for (int r = 0; r < 4; r++) {
                        const int tlr = wloc + g + ((r >> 1) << 3);
                        const int d = (s0 + nt * 8 + tg * 2 + (r & 1)) - (t0 + tlr);
                        if (d >= -4 && d <= 4) sPd[tlr * 12 + d + 4] = S[nt][r];
                    }
                }
                __syncwarp();
            }

#pragma unroll
            for (int ks = 0; ks < 4; ks++) {
                uint32_t aph[4], apl[4];
                pack_pair(S[2 * ks][0],     S[2 * ks][1],     aph[0], apl[0]);
                pack_pair(S[2 * ks][2],     S[2 * ks][3],     aph[1], apl[1]);
                pack_pair(S[2 * ks + 1][0], S[2 * ks + 1][1], aph[2], apl[2]);
                pack_pair(S[2 * ks + 1][2], S[2 * ks + 1][3], aph[3], apl[3]);
#pragma unroll
                for (int nt = 0; nt < 8; nt++) {
                    const int vr = (nt * 8 + g) * QSTR + ks * 16 + tg * 2;
                    uint32_t bh[2], bl[2];
                    bh[0] = ldb32(&sVh[vr]);
                    bh[1] = ldb32(&sVh[vr + 8]);
                    bl[0] = ldb32(&sVl[vr]);
                    bl[1] = ldb32(&sVl[vr + 8]);
                    MMA16816(O[nt], aph, bh);
                    MMA16816(O[nt], aph, bl);
                    MMA16816(O[nt], apl, bh);
                }
            }

            if (window) {
#pragma unroll
                for (int rh = 0; rh < 2; rh++) {
                    const int tlr = wloc + g + rh * 8;
#pragma unroll
                    for (int dd = 0; dd < 9; dd++) {
                        const float p = sPd[tlr * 12 + dd];
                        if (p != 0.f) {
#pragma unroll
                            for (int nt = 0; nt < 8; nt++) {
                                O[nt][2 * rh]     += p * sEV[dd * 64 + nt * 8 + tg * 2];
                                O[nt][2 * rh + 1] += p * sEV[dd * 64 + nt * 8 + tg * 2 + 1];
                            }
                        }
                    }
                }
            }
        }

        __syncthreads();   // sync4: all warps done reading sV / sPd

        // issue V(i+1) fill (overlaps next chunk's QK^T)
        if (has_next) {
            CP_ASYNC16(s2u(&sVh[fr0 * QSTR + fs0]), &Vh_b[(size_t)fr0 * Tv + sn + fs0]);
            CP_ASYNC16(s2u(&sVh[fr1 * QSTR + fs1]), &Vh_b[(size_t)fr1 * Tv + sn + fs1]);
            CP_ASYNC16(s2u(&sVl[fr0 * QSTR + fs0]), &Vl_b[(size_t)fr0 * Tv + sn + fs0]);
            CP_ASYNC16(s2u(&sVl[fr1 * QSTR + fs1]), &Vl_b[(size_t)fr1 * Tv + sn + fs1]);
            CP_COMMIT();
        }
    }

    // ---- finalize ----
    const float inv0 = 1.f / l0, inv1 = 1.f / l1;
    const size_t out0 = ((size_t)b * Tv + t0 + wloc + g) * Cv + h * 64;
    const size_t out1 = out0 + 8 * Cv;
#pragma unroll
    for (int nt = 0; nt < 8; nt++) {
        const int kc = nt * 8 + tg * 2;
        uint32_t hw, lw;
        pack_pair(O[nt][0] * inv0, O[nt][1] * inv0, hw, lw);
        *reinterpret_cast<uint32_t*>(&g_Xhi[out0 + kc]) = hw;
        *reinterpret_cast<uint32_t*>(&g_Xlo[out0 + kc]) = lw;
        pack_pair(O[nt][2] * inv1, O[nt][3] * inv1, hw, lw);
        *reinterpret_cast<uint32_t*>(&g_Xhi[out1 + kc]) = hw;
        *reinterpret_cast<uint32_t*>(&g_Xlo[out1 + kc]) = lw;
    }
}

// ---------------------------------------------------------------------------

extern "C" void kernel_launch(void* const* d_in, const int* in_sizes, int n_in,
                              void* d_out, int out_size)
{
    const float* x    = (const float*)d_in[0];
    const float* c    = (const float*)d_in[1];
    const float* mask = (const float*)d_in[2];
    const float* Wq   = (const float*)d_in[3];
    const float* bq   = (const float*)d_in[4];
    const float* Wk   = (const float*)d_in[5];
    const float* bk   = (const float*)d_in[6];
    const float* Wv   = (const float*)d_in[7];
    const float* bv   = (const float*)d_in[8];
    const float* Wo   = (const float*)d_in[9];
    const float* bo   = (const float*)d_in[10];
    const float* ek   = (const float*)d_in[11];
    const float* ev   = (const float*)d_in[12];
    float* out = (float*)d_out;

    __nv_bfloat16 *whi, *wlo, *xhi, *xlo, *chi, *clo, *qhi, *qlo, *khi, *klo, *vhi, *vlo;
    cudaGetSymbolAddress((void**)&whi, g_Whi);
    cudaGetSymbolAddress((void**)&wlo, g_Wlo);
    cudaGetSymbolAddress((void**)&xhi, g_Xhi);
    cudaGetSymbolAddress((void**)&xlo, g_Xlo);
    cudaGetSymbolAddress((void**)&chi, g_Chi);
    cudaGetSymbolAddress((void**)&clo, g_Clo);
    cudaGetSymbolAddress((void**)&qhi, g_Qhi);
    cudaGetSymbolAddress((void**)&qlo, g_Qlo);
    cudaGetSymbolAddress((void**)&khi, g_Khi);
    cudaGetSymbolAddress((void**)&klo, g_Klo);
    cudaGetSymbolAddress((void**)&vhi, g_Vhi);
    cudaGetSymbolAddress((void**)&vlo, g_Vlo);

    cudaFuncSetAttribute(attn_hmma, cudaFuncAttributeMaxDynamicSharedMemorySize,
                         ATTN_SMEM_BYTES);
    cudaFuncSetAttribute(hmma_gemm<0>, cudaFuncAttributeMaxDynamicSharedMemorySize,
                         GEMM_SMEM_BYTES);
    cudaFuncSetAttribute(hmma_gemm<1>, cudaFuncAttributeMaxDynamicSharedMemorySize,
                         GEMM_SMEM_BYTES);
    cudaFuncSetAttribute(hmma_gemm<2>, cudaFuncAttributeMaxDynamicSharedMemorySize,
                         GEMM_SMEM_BYTES);

    const int WSZ = Cv * Cv;

    // pre-passes
    dim3 wg(WSZ / 256, 4);
    convw4_kernel<<<wg, 256>>>(Wq, Wk, Wv, Wo);
    dim3 tg(Tv / 32, Cv / 32, 2 * Bv), tb(32, 8);
    tconv2_kernel<<<tg, tb>>>(x, c);
    maskbits_kernel<<<dim3(Tv / 8, Bv), 256>>>(mask);

    // projections: SEPARATE launches (L2 weight reuse per launch)
    hmma_gemm<0><<<dim3(Cv / 128, Tv / 128, Bv), 256, GEMM_SMEM_BYTES>>>(
        whi + 0 * WSZ, wlo + 0 * WSZ, xhi, xlo, bq, 0.125f, nullptr, qhi, qlo);
    hmma_gemm<0><<<dim3(Cv / 128, Tv / 128, Bv), 256, GEMM_SMEM_BYTES>>>(
        whi + 1 * WSZ, wlo + 1 * WSZ, chi, clo, bk, 1.0f, nullptr, khi, klo);
    hmma_gemm<1><<<dim3(Tv / 128, Cv / 128, Bv), 256, GEMM_SMEM_BYTES>>>(
        whi + 2 * WSZ, wlo + 2 * WSZ, chi, clo, bv, 1.0f, nullptr, vhi, vlo);

    // attention (writes split output into g_Xhi/g_Xlo)
    attn_hmma<<<dim3(Tv / 128, Hh, Bv), 256, ATTN_SMEM_BYTES>>>(ek, ev);

    // final projection (fp32 output)
    hmma_gemm<2><<<dim3(Tv / 128, Cv / 128, Bv), 256, GEMM_SMEM_BYTES>>>(
        whi + 3 * WSZ, wlo + 3 * WSZ, xhi, xlo, bo, 1.0f, out, nullptr, nullptr);
}